// round 1
// baseline (speedup 1.0000x reference)
#include <cuda_runtime.h>
#include <cuda_bf16.h>
#include <cstdint>

// ---------------- problem constants ----------------
#define BB 2
#define TT 2048
#define DD 1024
#define HH 16
#define KK 4
#define HD 64
#define CONV (3*DD)
#define MM (BB*TT)          // 4096 tokens

// ---------------- device scratch ----------------
__device__ float g_mixed[(size_t)MM * CONV];   // qkv pre-conv
__device__ float g_act[(size_t)MM * CONV];     // post conv+silu, then normalized q/k, v*beta
__device__ float g_z[(size_t)MM * DD];
__device__ float g_att[(size_t)MM * 2 * HH];   // raw dots: [0..15]=Wb, [16..31]=Wa
__device__ float g_eg[(size_t)MM * HH];        // exp(g)
__device__ float g_o[(size_t)MM * DD];         // scan output -> gated in place

// ---------------- SGEMM: C[M,N] = A[M,K] @ W[N,K]^T  (NT, all row-major) ----------------
#define BM 128
#define BN 128
#define BKT 8

__global__ __launch_bounds__(256) void sgemm_nt(const float* __restrict__ A,
                                                const float* __restrict__ W,
                                                float* __restrict__ C,
                                                int M, int N, int Kd) {
    __shared__ float As[BKT][BM + 4];
    __shared__ float Bs[BKT][BN + 4];
    int tid = threadIdx.x;
    int bm = blockIdx.y * BM;
    int bn = blockIdx.x * BN;

    int lr = tid >> 1;           // 0..127
    int lk = (tid & 1) * 4;      // 0 or 4
    int ty = tid >> 4;           // 0..15
    int tx = tid & 15;           // 0..15

    const float* Aptr = A + (size_t)(bm + lr) * Kd + lk;
    const float* Wptr = W + (size_t)(bn + lr) * Kd + lk;

    float acc[8][8];
#pragma unroll
    for (int i = 0; i < 8; i++)
#pragma unroll
        for (int j = 0; j < 8; j++) acc[i][j] = 0.f;

    float4 av = *(const float4*)(Aptr);
    float4 bv = *(const float4*)(Wptr);

    for (int k0 = 0; k0 < Kd; k0 += BKT) {
        As[lk + 0][lr] = av.x; As[lk + 1][lr] = av.y;
        As[lk + 2][lr] = av.z; As[lk + 3][lr] = av.w;
        Bs[lk + 0][lr] = bv.x; Bs[lk + 1][lr] = bv.y;
        Bs[lk + 2][lr] = bv.z; Bs[lk + 3][lr] = bv.w;
        __syncthreads();

        if (k0 + BKT < Kd) {
            av = *(const float4*)(Aptr + k0 + BKT);
            bv = *(const float4*)(Wptr + k0 + BKT);
        }

#pragma unroll
        for (int kk = 0; kk < BKT; kk++) {
            float af[8], bf[8];
            *(float4*)(af)     = *(const float4*)(&As[kk][ty * 8]);
            *(float4*)(af + 4) = *(const float4*)(&As[kk][ty * 8 + 4]);
            *(float4*)(bf)     = *(const float4*)(&Bs[kk][tx * 8]);
            *(float4*)(bf + 4) = *(const float4*)(&Bs[kk][tx * 8 + 4]);
#pragma unroll
            for (int i = 0; i < 8; i++)
#pragma unroll
                for (int j = 0; j < 8; j++)
                    acc[i][j] += af[i] * bf[j];
        }
        __syncthreads();
    }

#pragma unroll
    for (int i = 0; i < 8; i++) {
        float* crow = C + (size_t)(bm + ty * 8 + i) * N + bn + tx * 8;
        float4 v0 = make_float4(acc[i][0], acc[i][1], acc[i][2], acc[i][3]);
        float4 v1 = make_float4(acc[i][4], acc[i][5], acc[i][6], acc[i][7]);
        *(float4*)(crow)     = v0;
        *(float4*)(crow + 4) = v1;
    }
}

// ---------------- beta/g raw projections: att[m, 0..31] ----------------
__global__ __launch_bounds__(256) void att_kernel(const float* __restrict__ x,
                                                  const float* __restrict__ Wb,
                                                  const float* __restrict__ Wa,
                                                  float* __restrict__ att) {
    __shared__ float xs[DD];
    int m = blockIdx.x;
    int tid = threadIdx.x;
    *(float4*)&xs[tid * 4] = *(const float4*)(x + (size_t)m * DD + tid * 4);
    __syncthreads();

    int g = tid >> 3;     // 0..31
    int sub = tid & 7;
    const float* w = (g < HH) ? (Wb + (size_t)g * DD) : (Wa + (size_t)(g - HH) * DD);
    float s = 0.f;
    for (int j = sub * 4; j < DD; j += 32) {
        float4 wv = *(const float4*)(w + j);
        float4 xv = *(const float4*)(&xs[j]);
        s += wv.x * xv.x + wv.y * xv.y + wv.z * xv.z + wv.w * xv.w;
    }
    s += __shfl_xor_sync(0xffffffffu, s, 4);
    s += __shfl_xor_sync(0xffffffffu, s, 2);
    s += __shfl_xor_sync(0xffffffffu, s, 1);
    if (sub == 0) att[(size_t)m * 32 + g] = s;
}

// ---------------- causal depthwise conv (K=4) + SiLU ----------------
__global__ __launch_bounds__(256) void conv_silu_kernel(const float* __restrict__ mixed,
                                                        const float* __restrict__ cw,
                                                        float* __restrict__ out) {
    int idx = blockIdx.x * 256 + threadIdx.x;   // per (m, c4)
    int c4 = idx % (CONV / 4);
    int m  = idx / (CONV / 4);
    int t = m & (TT - 1);
    int c = c4 * 4;

    float4 w0 = *(const float4*)(cw + (size_t)(c + 0) * KK);
    float4 w1 = *(const float4*)(cw + (size_t)(c + 1) * KK);
    float4 w2 = *(const float4*)(cw + (size_t)(c + 2) * KK);
    float4 w3 = *(const float4*)(cw + (size_t)(c + 3) * KK);
    const float* wp0 = (const float*)&w0;
    const float* wp1 = (const float*)&w1;
    const float* wp2 = (const float*)&w2;
    const float* wp3 = (const float*)&w3;

    float a0 = 0.f, a1 = 0.f, a2 = 0.f, a3 = 0.f;
#pragma unroll
    for (int j = 0; j < KK; j++) {
        int tt = t + j - (KK - 1);
        if (tt >= 0) {
            float4 xv = *(const float4*)(mixed + (size_t)(m + j - (KK - 1)) * CONV + c);
            a0 += wp0[j] * xv.x;
            a1 += wp1[j] * xv.y;
            a2 += wp2[j] * xv.z;
            a3 += wp3[j] * xv.w;
        }
    }
    float4 r;
    r.x = a0 / (1.f + expf(-a0));
    r.y = a1 / (1.f + expf(-a1));
    r.z = a2 / (1.f + expf(-a2));
    r.w = a3 / (1.f + expf(-a3));
    *(float4*)(out + (size_t)m * CONV + c) = r;
}

// ---------------- per-(m,h): l2norm q/k, v*=beta, eg=exp(g) ----------------
__global__ __launch_bounds__(128) void prep_kernel(float* __restrict__ act,
                                                   const float* __restrict__ att,
                                                   const float* __restrict__ dt_bias,
                                                   const float* __restrict__ A_log,
                                                   float* __restrict__ eg) {
    int w = blockIdx.x * 4 + (threadIdx.x >> 5);
    int lane = threadIdx.x & 31;
    int m = w >> 4;
    int h = w & (HH - 1);
    float* base = act + (size_t)m * CONV + h * HD;

    // q
    float q0 = base[lane], q1 = base[lane + 32];
    float sq = q0 * q0 + q1 * q1;
#pragma unroll
    for (int o = 16; o; o >>= 1) sq += __shfl_xor_sync(0xffffffffu, sq, o);
    float invq = rsqrtf(sq + 1e-6f) * 0.125f;   // * HD^-0.5
    base[lane] = q0 * invq;
    base[lane + 32] = q1 * invq;

    // k
    float k0 = base[DD + lane], k1 = base[DD + lane + 32];
    float sk = k0 * k0 + k1 * k1;
#pragma unroll
    for (int o = 16; o; o >>= 1) sk += __shfl_xor_sync(0xffffffffu, sk, o);
    float invk = rsqrtf(sk + 1e-6f);
    base[DD + lane] = k0 * invk;
    base[DD + lane + 32] = k1 * invk;

    // beta, g
    float bdot = att[(size_t)m * 32 + h];
    float adot = att[(size_t)m * 32 + HH + h];
    float beta = 1.f / (1.f + expf(-bdot));
    float spin = adot + dt_bias[h];
    float sp = (spin > 20.f) ? spin : log1pf(expf(spin));
    float gg = -expf(A_log[h]) * sp;

    base[2 * DD + lane] *= beta;
    base[2 * DD + lane + 32] *= beta;
    if (lane == 0) eg[(size_t)m * HH + h] = expf(gg);
}

// ---------------- sequential gated scan ----------------
// grid 128 = 32 (b,h) * 4 col-groups ; 64 threads ; thread owns (col, part) with 16 d's
__global__ __launch_bounds__(64) void scan_kernel(const float* __restrict__ act,
                                                  const float* __restrict__ eg,
                                                  float* __restrict__ o) {
    int bh = blockIdx.x >> 2;
    int cg = blockIdx.x & 3;
    int b = bh >> 4;
    int h = bh & (HH - 1);
    int tid = threadIdx.x;
    int col = cg * 16 + (tid >> 2);
    int part = tid & 3;
    int dbase = part * 16;

    float S[16];
#pragma unroll
    for (int i = 0; i < 16; i++) S[i] = 0.f;

    const float* abase = act + (size_t)b * TT * CONV + h * HD;
    const float* ebase = eg + (size_t)b * TT * HH + h;
    float* obase = o + (size_t)b * TT * DD + h * HD + col;

    float4 q0[4], k0[4], q1[4], k1[4];
    float vb0, vb1, e0, e1;

#define LOADSTAGE(Q, Kv, VB, E, tstep)                                           \
    {                                                                            \
        const float* p = abase + (size_t)(tstep) * CONV;                         \
        const float4* pq = (const float4*)(p + dbase);                           \
        const float4* pk = (const float4*)(p + DD + dbase);                      \
        Q[0] = __ldg(pq + 0); Q[1] = __ldg(pq + 1);                              \
        Q[2] = __ldg(pq + 2); Q[3] = __ldg(pq + 3);                              \
        Kv[0] = __ldg(pk + 0); Kv[1] = __ldg(pk + 1);                            \
        Kv[2] = __ldg(pk + 2); Kv[3] = __ldg(pk + 3);                            \
        VB = __ldg(p + 2 * DD + col);                                            \
        E = __ldg(ebase + (size_t)(tstep) * HH);                                 \
    }

#define DOSTEP(Q, Kv, VB, E, tstep, PFQ, PFK, PFVB, PFE)                         \
    {                                                                            \
        float qq[16], kk[16];                                                    \
        *(float4*)(qq + 0)  = Q[0]; *(float4*)(qq + 4)  = Q[1];                  \
        *(float4*)(qq + 8)  = Q[2]; *(float4*)(qq + 12) = Q[3];                  \
        *(float4*)(kk + 0)  = Kv[0]; *(float4*)(kk + 4)  = Kv[1];                \
        *(float4*)(kk + 8)  = Kv[2]; *(float4*)(kk + 12) = Kv[3];                \
        float e = E, v = VB;                                                     \
        if ((tstep) + 2 < TT) LOADSTAGE(PFQ, PFK, PFVB, PFE, (tstep) + 2);       \
        float dot = 0.f;                                                         \
        _Pragma("unroll")                                                        \
        for (int i = 0; i < 16; i++) {                                           \
            S[i] = S[i] * e + kk[i] * v;                                         \
            dot += qq[i] * S[i];                                                 \
        }                                                                        \
        dot += __shfl_xor_sync(0xffffffffu, dot, 1);                             \
        dot += __shfl_xor_sync(0xffffffffu, dot, 2);                             \
        if (part == 0) obase[(size_t)(tstep) * DD] = dot;                        \
    }

    LOADSTAGE(q0, k0, vb0, e0, 0);
    LOADSTAGE(q1, k1, vb1, e1, 1);

    for (int t = 0; t < TT; t += 2) {
        DOSTEP(q0, k0, vb0, e0, t,     q0, k0, vb0, e0);
        DOSTEP(q1, k1, vb1, e1, t + 1, q1, k1, vb1, e1);
    }
#undef LOADSTAGE
#undef DOSTEP
}

// ---------------- gated RMSNorm over head dim ----------------
__global__ __launch_bounds__(128) void post_kernel(float* __restrict__ o,
                                                   const float* __restrict__ z) {
    int w = blockIdx.x * 4 + (threadIdx.x >> 5);
    int lane = threadIdx.x & 31;
    int m = w >> 4;
    int h = w & (HH - 1);
    float* ob = o + (size_t)m * DD + h * HD;
    const float* zb = z + (size_t)m * DD + h * HD;

    float o0 = ob[lane], o1 = ob[lane + 32];
    float s = o0 * o0 + o1 * o1;
#pragma unroll
    for (int off = 16; off; off >>= 1) s += __shfl_xor_sync(0xffffffffu, s, off);
    float r = rsqrtf(s * (1.f / 64.f) + 1e-6f);

    float z0 = zb[lane], z1 = zb[lane + 32];
    float g0 = z0 / (1.f + expf(-z0));
    float g1 = z1 / (1.f + expf(-z1));
    ob[lane] = o0 * r * g0;
    ob[lane + 32] = o1 * r * g1;
}

// ---------------- launch ----------------
extern "C" void kernel_launch(void* const* d_in, const int* in_sizes, int n_in,
                              void* d_out, int out_size) {
    const float* x       = (const float*)d_in[0];
    const float* W_qkv   = (const float*)d_in[1];
    const float* conv_w  = (const float*)d_in[2];
    const float* W_z     = (const float*)d_in[3];
    const float* W_b     = (const float*)d_in[4];
    const float* W_a     = (const float*)d_in[5];
    const float* dt_bias = (const float*)d_in[6];
    const float* A_log   = (const float*)d_in[7];
    const float* W_out   = (const float*)d_in[8];
    float* out = (float*)d_out;

    void *p_mixed, *p_act, *p_z, *p_att, *p_eg, *p_o;
    cudaGetSymbolAddress(&p_mixed, g_mixed);
    cudaGetSymbolAddress(&p_act,   g_act);
    cudaGetSymbolAddress(&p_z,     g_z);
    cudaGetSymbolAddress(&p_att,   g_att);
    cudaGetSymbolAddress(&p_eg,    g_eg);
    cudaGetSymbolAddress(&p_o,     g_o);
    float* mixed = (float*)p_mixed;
    float* act   = (float*)p_act;
    float* zbuf  = (float*)p_z;
    float* att   = (float*)p_att;
    float* egb   = (float*)p_eg;
    float* obuf  = (float*)p_o;

    // 1. qkv projection: [4096,3072]
    sgemm_nt<<<dim3(CONV / BN, MM / BM), 256>>>(x, W_qkv, mixed, MM, CONV, DD);
    // 2. z projection: [4096,1024]
    sgemm_nt<<<dim3(DD / BN, MM / BM), 256>>>(x, W_z, zbuf, MM, DD, DD);
    // 3. beta/g raw dots
    att_kernel<<<MM, 256>>>(x, W_b, W_a, att);
    // 4. causal depthwise conv + silu
    conv_silu_kernel<<<(MM * (CONV / 4)) / 256, 256>>>(mixed, conv_w, act);
    // 5. l2norm q/k, v*beta, eg
    prep_kernel<<<(MM * HH) / 4, 128>>>(act, att, dt_bias, A_log, egb);
    // 6. sequential scan
    scan_kernel<<<BB * HH * 4, 64>>>(act, egb, obuf);
    // 7. gated rmsnorm
    post_kernel<<<(MM * HH) / 4, 128>>>(obuf, zbuf);
    // 8. output projection -> d_out
    sgemm_nt<<<dim3(DD / BN, MM / BM), 256>>>(obuf, W_out, out, MM, DD, DD);
}

// round 2
// speedup vs baseline: 1.6225x; 1.6225x over previous
#include <cuda_runtime.h>
#include <cuda_bf16.h>
#include <cstdint>

// ---------------- problem constants ----------------
#define BB 2
#define TT 2048
#define DD 1024
#define HH 16
#define KK 4
#define HD 64
#define CONV (3*DD)
#define MM (BB*TT)          // 4096 tokens

// ---------------- device scratch ----------------
__device__ float g_mixed[(size_t)MM * CONV];   // qkv pre-conv
__device__ float g_act[(size_t)MM * CONV];     // post conv+silu, then normalized q/k, v*beta
__device__ float g_z[(size_t)MM * DD];
__device__ float g_att[(size_t)MM * 2 * HH];   // raw dots: [0..15]=Wb, [16..31]=Wa
__device__ float g_eg[(size_t)MM * HH];        // exp(g)
__device__ float g_o[(size_t)MM * DD];         // scan output -> gated in place

// ---------------- tf32 tensor-core GEMM: C[M,N] = A[M,K] @ W[N,K]^T ----------------
// Block 128x128x32, 256 threads = 8 warps (2x4), warp tile 64x32.
#define GBM 128
#define GBN 128
#define GBK 32
#define KPAD 4
#define KST (GBK + KPAD)   // smem row stride = 36 -> conflict-free frag loads

__device__ __forceinline__ uint32_t f2tf32(float x) {
    uint32_t u;
    asm("cvt.rna.tf32.f32 %0, %1;" : "=r"(u) : "f"(x));
    return u;
}

__global__ __launch_bounds__(256) void tgemm_nt(const float* __restrict__ A,
                                                const float* __restrict__ W,
                                                float* __restrict__ C,
                                                int M, int N, int Kd) {
    __shared__ uint32_t As[GBM][KST];
    __shared__ uint32_t Bs[GBN][KST];

    int tid = threadIdx.x;
    int wid = tid >> 5;
    int lane = tid & 31;
    int bm = blockIdx.y * GBM;
    int bn = blockIdx.x * GBN;
    int wm = (wid & 1) * 64;       // warp row offset in block tile
    int wn = (wid >> 1) * 32;      // warp col offset
    int g = lane >> 2;             // 0..7
    int tg = lane & 3;             // 0..3

    // staging: 256 threads load 128 rows x 32 k (8 float4 per row)
    int lrow = tid >> 3;           // 0..31 (+32p covers 128 rows)
    int lk = (tid & 7) * 4;

    const float* Aptr = A + (size_t)(bm + lrow) * Kd + lk;
    const float* Wptr = W + (size_t)(bn + lrow) * Kd + lk;

    float acc[4][4][4];            // [mi][ni][c0..c3]
#pragma unroll
    for (int i = 0; i < 4; i++)
#pragma unroll
        for (int j = 0; j < 4; j++)
#pragma unroll
            for (int c = 0; c < 4; c++) acc[i][j][c] = 0.f;

    float4 ar[4], br[4];
#pragma unroll
    for (int p = 0; p < 4; p++) {
        ar[p] = *(const float4*)(Aptr + (size_t)(p * 32) * Kd);
        br[p] = *(const float4*)(Wptr + (size_t)(p * 32) * Kd);
    }

    for (int k0 = 0; k0 < Kd; k0 += GBK) {
#pragma unroll
        for (int p = 0; p < 4; p++) {
            uint4 av = make_uint4(f2tf32(ar[p].x), f2tf32(ar[p].y),
                                  f2tf32(ar[p].z), f2tf32(ar[p].w));
            uint4 bv = make_uint4(f2tf32(br[p].x), f2tf32(br[p].y),
                                  f2tf32(br[p].z), f2tf32(br[p].w));
            *(uint4*)(&As[lrow + p * 32][lk]) = av;
            *(uint4*)(&Bs[lrow + p * 32][lk]) = bv;
        }
        __syncthreads();

        if (k0 + GBK < Kd) {
#pragma unroll
            for (int p = 0; p < 4; p++) {
                ar[p] = *(const float4*)(Aptr + (size_t)(p * 32) * Kd + k0 + GBK);
                br[p] = *(const float4*)(Wptr + (size_t)(p * 32) * Kd + k0 + GBK);
            }
        }

#pragma unroll
        for (int kk = 0; kk < GBK; kk += 8) {
            uint32_t af[4][4];
            uint32_t bf[4][2];
#pragma unroll
            for (int mi = 0; mi < 4; mi++) {
                int r = wm + mi * 16;
                af[mi][0] = As[r + g][kk + tg];
                af[mi][1] = As[r + g + 8][kk + tg];
                af[mi][2] = As[r + g][kk + tg + 4];
                af[mi][3] = As[r + g + 8][kk + tg + 4];
            }
#pragma unroll
            for (int ni = 0; ni < 4; ni++) {
                int r = wn + ni * 8;
                bf[ni][0] = Bs[r + g][kk + tg];
                bf[ni][1] = Bs[r + g][kk + tg + 4];
            }
#pragma unroll
            for (int mi = 0; mi < 4; mi++)
#pragma unroll
                for (int ni = 0; ni < 4; ni++) {
                    asm volatile(
                        "mma.sync.aligned.m16n8k8.row.col.f32.tf32.tf32.f32 "
                        "{%0,%1,%2,%3}, {%4,%5,%6,%7}, {%8,%9}, {%0,%1,%2,%3};"
                        : "+f"(acc[mi][ni][0]), "+f"(acc[mi][ni][1]),
                          "+f"(acc[mi][ni][2]), "+f"(acc[mi][ni][3])
                        : "r"(af[mi][0]), "r"(af[mi][1]), "r"(af[mi][2]), "r"(af[mi][3]),
                          "r"(bf[ni][0]), "r"(bf[ni][1]));
                }
        }
        __syncthreads();
    }

    // epilogue
#pragma unroll
    for (int mi = 0; mi < 4; mi++) {
#pragma unroll
        for (int ni = 0; ni < 4; ni++) {
            int row0 = bm + wm + mi * 16 + g;
            int col = bn + wn + ni * 8 + tg * 2;
            *(float2*)(C + (size_t)row0 * N + col) =
                make_float2(acc[mi][ni][0], acc[mi][ni][1]);
            *(float2*)(C + (size_t)(row0 + 8) * N + col) =
                make_float2(acc[mi][ni][2], acc[mi][ni][3]);
        }
    }
}

// ---------------- beta/g raw projections: att[m, 0..31] ----------------
__global__ __launch_bounds__(256) void att_kernel(const float* __restrict__ x,
                                                  const float* __restrict__ Wb,
                                                  const float* __restrict__ Wa,
                                                  float* __restrict__ att) {
    __shared__ float xs[DD];
    int m = blockIdx.x;
    int tid = threadIdx.x;
    *(float4*)&xs[tid * 4] = *(const float4*)(x + (size_t)m * DD + tid * 4);
    __syncthreads();

    int g = tid >> 3;     // 0..31
    int sub = tid & 7;
    const float* w = (g < HH) ? (Wb + (size_t)g * DD) : (Wa + (size_t)(g - HH) * DD);
    float s = 0.f;
    for (int j = sub * 4; j < DD; j += 32) {
        float4 wv = *(const float4*)(w + j);
        float4 xv = *(const float4*)(&xs[j]);
        s += wv.x * xv.x + wv.y * xv.y + wv.z * xv.z + wv.w * xv.w;
    }
    s += __shfl_xor_sync(0xffffffffu, s, 4);
    s += __shfl_xor_sync(0xffffffffu, s, 2);
    s += __shfl_xor_sync(0xffffffffu, s, 1);
    if (sub == 0) att[(size_t)m * 32 + g] = s;
}

// ---------------- causal depthwise conv (K=4) + SiLU ----------------
__global__ __launch_bounds__(256) void conv_silu_kernel(const float* __restrict__ mixed,
                                                        const float* __restrict__ cw,
                                                        float* __restrict__ out) {
    int idx = blockIdx.x * 256 + threadIdx.x;   // per (m, c4)
    int c4 = idx % (CONV / 4);
    int m  = idx / (CONV / 4);
    int t = m & (TT - 1);
    int c = c4 * 4;

    float4 w0 = *(const float4*)(cw + (size_t)(c + 0) * KK);
    float4 w1 = *(const float4*)(cw + (size_t)(c + 1) * KK);
    float4 w2 = *(const float4*)(cw + (size_t)(c + 2) * KK);
    float4 w3 = *(const float4*)(cw + (size_t)(c + 3) * KK);
    const float* wp0 = (const float*)&w0;
    const float* wp1 = (const float*)&w1;
    const float* wp2 = (const float*)&w2;
    const float* wp3 = (const float*)&w3;

    float a0 = 0.f, a1 = 0.f, a2 = 0.f, a3 = 0.f;
#pragma unroll
    for (int j = 0; j < KK; j++) {
        int tt = t + j - (KK - 1);
        if (tt >= 0) {
            float4 xv = *(const float4*)(mixed + (size_t)(m + j - (KK - 1)) * CONV + c);
            a0 += wp0[j] * xv.x;
            a1 += wp1[j] * xv.y;
            a2 += wp2[j] * xv.z;
            a3 += wp3[j] * xv.w;
        }
    }
    float4 r;
    r.x = a0 / (1.f + expf(-a0));
    r.y = a1 / (1.f + expf(-a1));
    r.z = a2 / (1.f + expf(-a2));
    r.w = a3 / (1.f + expf(-a3));
    *(float4*)(out + (size_t)m * CONV + c) = r;
}

// ---------------- per-(m,h): l2norm q/k, v*=beta, eg=exp(g) ----------------
__global__ __launch_bounds__(128) void prep_kernel(float* __restrict__ act,
                                                   const float* __restrict__ att,
                                                   const float* __restrict__ dt_bias,
                                                   const float* __restrict__ A_log,
                                                   float* __restrict__ eg) {
    int w = blockIdx.x * 4 + (threadIdx.x >> 5);
    int lane = threadIdx.x & 31;
    int m = w >> 4;
    int h = w & (HH - 1);
    float* base = act + (size_t)m * CONV + h * HD;

    // q
    float q0 = base[lane], q1 = base[lane + 32];
    float sq = q0 * q0 + q1 * q1;
#pragma unroll
    for (int o = 16; o; o >>= 1) sq += __shfl_xor_sync(0xffffffffu, sq, o);
    float invq = rsqrtf(sq + 1e-6f) * 0.125f;   // * HD^-0.5
    base[lane] = q0 * invq;
    base[lane + 32] = q1 * invq;

    // k
    float k0 = base[DD + lane], k1 = base[DD + lane + 32];
    float sk = k0 * k0 + k1 * k1;
#pragma unroll
    for (int o = 16; o; o >>= 1) sk += __shfl_xor_sync(0xffffffffu, sk, o);
    float invk = rsqrtf(sk + 1e-6f);
    base[DD + lane] = k0 * invk;
    base[DD + lane + 32] = k1 * invk;

    // beta, g
    float bdot = att[(size_t)m * 32 + h];
    float adot = att[(size_t)m * 32 + HH + h];
    float beta = 1.f / (1.f + expf(-bdot));
    float spin = adot + dt_bias[h];
    float sp = (spin > 20.f) ? spin : log1pf(expf(spin));
    float gg = -expf(A_log[h]) * sp;

    base[2 * DD + lane] *= beta;
    base[2 * DD + lane + 32] *= beta;
    if (lane == 0) eg[(size_t)m * HH + h] = expf(gg);
}

// ---------------- sequential gated scan ----------------
// grid 128 = 32 (b,h) * 4 col-groups ; 64 threads ; thread owns (col, part) with 16 d's
__global__ __launch_bounds__(64) void scan_kernel(const float* __restrict__ act,
                                                  const float* __restrict__ eg,
                                                  float* __restrict__ o) {
    int bh = blockIdx.x >> 2;
    int cg = blockIdx.x & 3;
    int b = bh >> 4;
    int h = bh & (HH - 1);
    int tid = threadIdx.x;
    int col = cg * 16 + (tid >> 2);
    int part = tid & 3;
    int dbase = part * 16;

    float S[16];
#pragma unroll
    for (int i = 0; i < 16; i++) S[i] = 0.f;

    const float* abase = act + (size_t)b * TT * CONV + h * HD;
    const float* ebase = eg + (size_t)b * TT * HH + h;
    float* obase = o + (size_t)b * TT * DD + h * HD + col;

    float4 q0[4], k0[4], q1[4], k1[4];
    float vb0, vb1, e0, e1;

#define LOADSTAGE(Q, Kv, VB, E, tstep)                                           \
    {                                                                            \
        const float* p = abase + (size_t)(tstep) * CONV;                         \
        const float4* pq = (const float4*)(p + dbase);                           \
        const float4* pk = (const float4*)(p + DD + dbase);                      \
        Q[0] = __ldg(pq + 0); Q[1] = __ldg(pq + 1);                              \
        Q[2] = __ldg(pq + 2); Q[3] = __ldg(pq + 3);                              \
        Kv[0] = __ldg(pk + 0); Kv[1] = __ldg(pk + 1);                            \
        Kv[2] = __ldg(pk + 2); Kv[3] = __ldg(pk + 3);                            \
        VB = __ldg(p + 2 * DD + col);                                            \
        E = __ldg(ebase + (size_t)(tstep) * HH);                                 \
    }

#define DOSTEP(Q, Kv, VB, E, tstep, PFQ, PFK, PFVB, PFE)                         \
    {                                                                            \
        float qq[16], kk[16];                                                    \
        *(float4*)(qq + 0)  = Q[0]; *(float4*)(qq + 4)  = Q[1];                  \
        *(float4*)(qq + 8)  = Q[2]; *(float4*)(qq + 12) = Q[3];                  \
        *(float4*)(kk + 0)  = Kv[0]; *(float4*)(kk + 4)  = Kv[1];                \
        *(float4*)(kk + 8)  = Kv[2]; *(float4*)(kk + 12) = Kv[3];                \
        float e = E, v = VB;                                                     \
        if ((tstep) + 2 < TT) LOADSTAGE(PFQ, PFK, PFVB, PFE, (tstep) + 2);       \
        float dot = 0.f;                                                         \
        _Pragma("unroll")                                                        \
        for (int i = 0; i < 16; i++) {                                           \
            S[i] = S[i] * e + kk[i] * v;                                         \
            dot += qq[i] * S[i];                                                 \
        }                                                                        \
        dot += __shfl_xor_sync(0xffffffffu, dot, 1);                             \
        dot += __shfl_xor_sync(0xffffffffu, dot, 2);                             \
        if (part == 0) obase[(size_t)(tstep) * DD] = dot;                        \
    }

    LOADSTAGE(q0, k0, vb0, e0, 0);
    LOADSTAGE(q1, k1, vb1, e1, 1);

    for (int t = 0; t < TT; t += 2) {
        DOSTEP(q0, k0, vb0, e0, t,     q0, k0, vb0, e0);
        DOSTEP(q1, k1, vb1, e1, t + 1, q1, k1, vb1, e1);
    }
#undef LOADSTAGE
#undef DOSTEP
}

// ---------------- gated RMSNorm over head dim ----------------
__global__ __launch_bounds__(128) void post_kernel(float* __restrict__ o,
                                                   const float* __restrict__ z) {
    int w = blockIdx.x * 4 + (threadIdx.x >> 5);
    int lane = threadIdx.x & 31;
    int m = w >> 4;
    int h = w & (HH - 1);
    float* ob = o + (size_t)m * DD + h * HD;
    const float* zb = z + (size_t)m * DD + h * HD;

    float o0 = ob[lane], o1 = ob[lane + 32];
    float s = o0 * o0 + o1 * o1;
#pragma unroll
    for (int off = 16; off; off >>= 1) s += __shfl_xor_sync(0xffffffffu, s, off);
    float r = rsqrtf(s * (1.f / 64.f) + 1e-6f);

    float z0 = zb[lane], z1 = zb[lane + 32];
    float g0 = z0 / (1.f + expf(-z0));
    float g1 = z1 / (1.f + expf(-z1));
    ob[lane] = o0 * r * g0;
    ob[lane + 32] = o1 * r * g1;
}

// ---------------- launch ----------------
extern "C" void kernel_launch(void* const* d_in, const int* in_sizes, int n_in,
                              void* d_out, int out_size) {
    const float* x       = (const float*)d_in[0];
    const float* W_qkv   = (const float*)d_in[1];
    const float* conv_w  = (const float*)d_in[2];
    const float* W_z     = (const float*)d_in[3];
    const float* W_b     = (const float*)d_in[4];
    const float* W_a     = (const float*)d_in[5];
    const float* dt_bias = (const float*)d_in[6];
    const float* A_log   = (const float*)d_in[7];
    const float* W_out   = (const float*)d_in[8];
    float* out = (float*)d_out;

    void *p_mixed, *p_act, *p_z, *p_att, *p_eg, *p_o;
    cudaGetSymbolAddress(&p_mixed, g_mixed);
    cudaGetSymbolAddress(&p_act,   g_act);
    cudaGetSymbolAddress(&p_z,     g_z);
    cudaGetSymbolAddress(&p_att,   g_att);
    cudaGetSymbolAddress(&p_eg,    g_eg);
    cudaGetSymbolAddress(&p_o,     g_o);
    float* mixed = (float*)p_mixed;
    float* act   = (float*)p_act;
    float* zbuf  = (float*)p_z;
    float* att   = (float*)p_att;
    float* egb   = (float*)p_eg;
    float* obuf  = (float*)p_o;

    // 1. qkv projection: [4096,3072]  (tensor cores, tf32)
    tgemm_nt<<<dim3(CONV / GBN, MM / GBM), 256>>>(x, W_qkv, mixed, MM, CONV, DD);
    // 2. z projection: [4096,1024]
    tgemm_nt<<<dim3(DD / GBN, MM / GBM), 256>>>(x, W_z, zbuf, MM, DD, DD);
    // 3. beta/g raw dots
    att_kernel<<<MM, 256>>>(x, W_b, W_a, att);
    // 4. causal depthwise conv + silu
    conv_silu_kernel<<<(MM * (CONV / 4)) / 256, 256>>>(mixed, conv_w, act);
    // 5. l2norm q/k, v*beta, eg
    prep_kernel<<<(MM * HH) / 4, 128>>>(act, att, dt_bias, A_log, egb);
    // 6. sequential scan
    scan_kernel<<<BB * HH * 4, 64>>>(act, egb, obuf);
    // 7. gated rmsnorm
    post_kernel<<<(MM * HH) / 4, 128>>>(obuf, zbuf);
    // 8. output projection -> d_out
    tgemm_nt<<<dim3(DD / GBN, MM / GBM), 256>>>(obuf, W_out, out, MM, DD, DD);
}

// round 3
// speedup vs baseline: 2.1995x; 1.3556x over previous
#include <cuda_runtime.h>
#include <cuda_bf16.h>
#include <cstdint>

// ---------------- problem constants ----------------
#define BB 2
#define TT 2048
#define DD 1024
#define HH 16
#define KK 4
#define HD 64
#define CONV (3*DD)
#define MM (BB*TT)          // 4096 tokens

// ---------------- device scratch ----------------
__device__ float g_mixed[(size_t)MM * CONV];   // qkv pre-conv
__device__ float g_act[(size_t)MM * CONV];     // post conv+silu, then normalized q/k, v*beta
__device__ float g_z[(size_t)MM * DD];
__device__ float g_att[(size_t)MM * 2 * HH];   // raw dots: [0..15]=Wb, [16..31]=Wa
__device__ float g_eg[(size_t)MM * HH];        // exp(g)
__device__ float g_o[(size_t)MM * DD];         // scan output -> gated in place

// ---------------- tf32 tensor-core GEMM: C[M,N] = A[M,K] @ W[N,K]^T ----------------
// Block 128x128x32, 256 threads = 8 warps (2x4), warp tile 64x32.
// Double-buffered dynamic smem (72KB), one __syncthreads per k-tile.
#define GBM 128
#define GBN 128
#define GBK 32
#define KPAD 4
#define KST (GBK + KPAD)        // 36 -> conflict-free frag loads
#define ATILE (GBM * KST)       // 4608 words
#define BTILE (GBN * KST)
#define BUFW (ATILE + BTILE)    // words per buffer
#define GSMEM (2 * BUFW * 4)    // 73728 bytes

__device__ __forceinline__ uint32_t f2tf32(float x) {
    uint32_t u;
    asm("cvt.rna.tf32.f32 %0, %1;" : "=r"(u) : "f"(x));
    return u;
}

__global__ __launch_bounds__(256) void tgemm_nt(const float* __restrict__ A,
                                                const float* __restrict__ W,
                                                float* __restrict__ C,
                                                int M, int N, int Kd) {
    extern __shared__ uint32_t sm[];

    int tid = threadIdx.x;
    int wid = tid >> 5;
    int lane = tid & 31;
    int bm = blockIdx.y * GBM;
    int bn = blockIdx.x * GBN;
    int wm = (wid & 1) * 64;       // warp row offset in block tile
    int wn = (wid >> 1) * 32;      // warp col offset
    int g = lane >> 2;             // 0..7
    int tg = lane & 3;             // 0..3

    // staging: 256 threads load 128 rows x 32 k (8 float4 per row)
    int lrow = tid >> 3;           // 0..31 (+32p covers 128 rows)
    int lk = (tid & 7) * 4;

    const float* Aptr = A + (size_t)(bm + lrow) * Kd + lk;
    const float* Wptr = W + (size_t)(bn + lrow) * Kd + lk;

    float acc[4][4][4];            // [mi][ni][c0..c3]
#pragma unroll
    for (int i = 0; i < 4; i++)
#pragma unroll
        for (int j = 0; j < 4; j++)
#pragma unroll
            for (int c = 0; c < 4; c++) acc[i][j][c] = 0.f;

    float4 ar[4], br[4];
#pragma unroll
    for (int p = 0; p < 4; p++) {
        ar[p] = *(const float4*)(Aptr + (size_t)(p * 32) * Kd);
        br[p] = *(const float4*)(Wptr + (size_t)(p * 32) * Kd);
    }

    // stage tile 0 into buffer 0
    {
        uint32_t* As = sm;
        uint32_t* Bs = sm + ATILE;
#pragma unroll
        for (int p = 0; p < 4; p++) {
            uint4 av = make_uint4(f2tf32(ar[p].x), f2tf32(ar[p].y),
                                  f2tf32(ar[p].z), f2tf32(ar[p].w));
            uint4 bv = make_uint4(f2tf32(br[p].x), f2tf32(br[p].y),
                                  f2tf32(br[p].z), f2tf32(br[p].w));
            *(uint4*)(&As[(lrow + p * 32) * KST + lk]) = av;
            *(uint4*)(&Bs[(lrow + p * 32) * KST + lk]) = bv;
        }
    }
    __syncthreads();

    int ntile = Kd / GBK;
    for (int it = 0; it < ntile; it++) {
        uint32_t* As = sm + (it & 1) * BUFW;
        uint32_t* Bs = As + ATILE;
        bool more = (it + 1) < ntile;

        if (more) {
            int ko = (it + 1) * GBK;
#pragma unroll
            for (int p = 0; p < 4; p++) {
                ar[p] = *(const float4*)(Aptr + (size_t)(p * 32) * Kd + ko);
                br[p] = *(const float4*)(Wptr + (size_t)(p * 32) * Kd + ko);
            }
        }

#pragma unroll
        for (int kk = 0; kk < GBK; kk += 8) {
            uint32_t af[4][4];
            uint32_t bf[4][2];
#pragma unroll
            for (int mi = 0; mi < 4; mi++) {
                int r = wm + mi * 16;
                af[mi][0] = As[(r + g) * KST + kk + tg];
                af[mi][1] = As[(r + g + 8) * KST + kk + tg];
                af[mi][2] = As[(r + g) * KST + kk + tg + 4];
                af[mi][3] = As[(r + g + 8) * KST + kk + tg + 4];
            }
#pragma unroll
            for (int ni = 0; ni < 4; ni++) {
                int r = wn + ni * 8;
                bf[ni][0] = Bs[(r + g) * KST + kk + tg];
                bf[ni][1] = Bs[(r + g) * KST + kk + tg + 4];
            }
#pragma unroll
            for (int mi = 0; mi < 4; mi++)
#pragma unroll
                for (int ni = 0; ni < 4; ni++) {
                    asm volatile(
                        "mma.sync.aligned.m16n8k8.row.col.f32.tf32.tf32.f32 "
                        "{%0,%1,%2,%3}, {%4,%5,%6,%7}, {%8,%9}, {%0,%1,%2,%3};"
                        : "+f"(acc[mi][ni][0]), "+f"(acc[mi][ni][1]),
                          "+f"(acc[mi][ni][2]), "+f"(acc[mi][ni][3])
                        : "r"(af[mi][0]), "r"(af[mi][1]), "r"(af[mi][2]), "r"(af[mi][3]),
                          "r"(bf[ni][0]), "r"(bf[ni][1]));
                }
        }

        if (more) {
            uint32_t* An = sm + ((it + 1) & 1) * BUFW;
            uint32_t* Bn = An + ATILE;
#pragma unroll
            for (int p = 0; p < 4; p++) {
                uint4 av = make_uint4(f2tf32(ar[p].x), f2tf32(ar[p].y),
                                      f2tf32(ar[p].z), f2tf32(ar[p].w));
                uint4 bv = make_uint4(f2tf32(br[p].x), f2tf32(br[p].y),
                                      f2tf32(br[p].z), f2tf32(br[p].w));
                *(uint4*)(&An[(lrow + p * 32) * KST + lk]) = av;
                *(uint4*)(&Bn[(lrow + p * 32) * KST + lk]) = bv;
            }
            __syncthreads();
        }
    }

    // epilogue
#pragma unroll
    for (int mi = 0; mi < 4; mi++) {
#pragma unroll
        for (int ni = 0; ni < 4; ni++) {
            int row0 = bm + wm + mi * 16 + g;
            int col = bn + wn + ni * 8 + tg * 2;
            *(float2*)(C + (size_t)row0 * N + col) =
                make_float2(acc[mi][ni][0], acc[mi][ni][1]);
            *(float2*)(C + (size_t)(row0 + 8) * N + col) =
                make_float2(acc[mi][ni][2], acc[mi][ni][3]);
        }
    }
}

// ---------------- beta/g raw projections: att[m, 0..31] ----------------
__global__ __launch_bounds__(256) void att_kernel(const float* __restrict__ x,
                                                  const float* __restrict__ Wb,
                                                  const float* __restrict__ Wa,
                                                  float* __restrict__ att) {
    __shared__ float xs[DD];
    int m = blockIdx.x;
    int tid = threadIdx.x;
    *(float4*)&xs[tid * 4] = *(const float4*)(x + (size_t)m * DD + tid * 4);
    __syncthreads();

    int g = tid >> 3;     // 0..31
    int sub = tid & 7;
    const float* w = (g < HH) ? (Wb + (size_t)g * DD) : (Wa + (size_t)(g - HH) * DD);
    float s = 0.f;
    for (int j = sub * 4; j < DD; j += 32) {
        float4 wv = *(const float4*)(w + j);
        float4 xv = *(const float4*)(&xs[j]);
        s += wv.x * xv.x + wv.y * xv.y + wv.z * xv.z + wv.w * xv.w;
    }
    s += __shfl_xor_sync(0xffffffffu, s, 4);
    s += __shfl_xor_sync(0xffffffffu, s, 2);
    s += __shfl_xor_sync(0xffffffffu, s, 1);
    if (sub == 0) att[(size_t)m * 32 + g] = s;
}

// ---------------- causal depthwise conv (K=4) + SiLU, strip-mined 8 t/thread ----------------
__global__ __launch_bounds__(256) void conv_silu_kernel(const float* __restrict__ mixed,
                                                        const float* __restrict__ cw,
                                                        float* __restrict__ out) {
    int idx = blockIdx.x * 256 + threadIdx.x;   // over (MM/8) * (CONV/4)
    int c4 = idx % (CONV / 4);
    int mb = idx / (CONV / 4);
    int m0 = mb * 8;
    int t0 = m0 & (TT - 1);
    int c = c4 * 4;

    float4 w0 = *(const float4*)(cw + (size_t)(c + 0) * KK);
    float4 w1 = *(const float4*)(cw + (size_t)(c + 1) * KK);
    float4 w2 = *(const float4*)(cw + (size_t)(c + 2) * KK);
    float4 w3 = *(const float4*)(cw + (size_t)(c + 3) * KK);
    const float* wp0 = (const float*)&w0;
    const float* wp1 = (const float*)&w1;
    const float* wp2 = (const float*)&w2;
    const float* wp3 = (const float*)&w3;

    float4 win[4];  // rows t-3..t
    const float4 zero4 = make_float4(0.f, 0.f, 0.f, 0.f);
#pragma unroll
    for (int s = 0; s < 3; s++) {
        win[s] = (t0 - 3 + s >= 0)
               ? *(const float4*)(mixed + (size_t)(m0 - 3 + s) * CONV + c)
               : zero4;
    }

#pragma unroll
    for (int tt = 0; tt < 8; tt++) {
        win[3] = *(const float4*)(mixed + (size_t)(m0 + tt) * CONV + c);
        float a0 = 0.f, a1 = 0.f, a2 = 0.f, a3 = 0.f;
#pragma unroll
        for (int j = 0; j < KK; j++) {
            a0 += wp0[j] * win[j].x;
            a1 += wp1[j] * win[j].y;
            a2 += wp2[j] * win[j].z;
            a3 += wp3[j] * win[j].w;
        }
        float4 r;
        r.x = a0 / (1.f + expf(-a0));
        r.y = a1 / (1.f + expf(-a1));
        r.z = a2 / (1.f + expf(-a2));
        r.w = a3 / (1.f + expf(-a3));
        *(float4*)(out + (size_t)(m0 + tt) * CONV + c) = r;
        win[0] = win[1]; win[1] = win[2]; win[2] = win[3];
    }
}

// ---------------- per-(m,h): l2norm q/k, v*=beta, eg=exp(g) ----------------
__global__ __launch_bounds__(128) void prep_kernel(float* __restrict__ act,
                                                   const float* __restrict__ att,
                                                   const float* __restrict__ dt_bias,
                                                   const float* __restrict__ A_log,
                                                   float* __restrict__ eg) {
    int w = blockIdx.x * 4 + (threadIdx.x >> 5);
    int lane = threadIdx.x & 31;
    int m = w >> 4;
    int h = w & (HH - 1);
    float* base = act + (size_t)m * CONV + h * HD;

    // q
    float q0 = base[lane], q1 = base[lane + 32];
    float sq = q0 * q0 + q1 * q1;
#pragma unroll
    for (int o = 16; o; o >>= 1) sq += __shfl_xor_sync(0xffffffffu, sq, o);
    float invq = rsqrtf(sq + 1e-6f) * 0.125f;   // * HD^-0.5
    base[lane] = q0 * invq;
    base[lane + 32] = q1 * invq;

    // k
    float k0 = base[DD + lane], k1 = base[DD + lane + 32];
    float sk = k0 * k0 + k1 * k1;
#pragma unroll
    for (int o = 16; o; o >>= 1) sk += __shfl_xor_sync(0xffffffffu, sk, o);
    float invk = rsqrtf(sk + 1e-6f);
    base[DD + lane] = k0 * invk;
    base[DD + lane + 32] = k1 * invk;

    // beta, g
    float bdot = att[(size_t)m * 32 + h];
    float adot = att[(size_t)m * 32 + HH + h];
    float beta = 1.f / (1.f + expf(-bdot));
    float spin = adot + dt_bias[h];
    float sp = (spin > 20.f) ? spin : log1pf(expf(spin));
    float gg = -expf(A_log[h]) * sp;

    base[2 * DD + lane] *= beta;
    base[2 * DD + lane + 32] *= beta;
    if (lane == 0) eg[(size_t)m * HH + h] = expf(gg);
}

// ---------------- sequential gated scan ----------------
// grid 256 = 32 (b,h) * 8 col-groups ; 64 threads ; thread owns (col, part) with 8 d's
__global__ __launch_bounds__(64) void scan_kernel(const float* __restrict__ act,
                                                  const float* __restrict__ eg,
                                                  float* __restrict__ o) {
    int bh = blockIdx.x >> 3;
    int cg = blockIdx.x & 7;
    int b = bh >> 4;
    int h = bh & (HH - 1);
    int tid = threadIdx.x;
    int col = cg * 8 + (tid >> 3);
    int part = tid & 7;
    int dbase = part * 8;

    float S[8];
#pragma unroll
    for (int i = 0; i < 8; i++) S[i] = 0.f;

    const float* abase = act + (size_t)b * TT * CONV + h * HD;
    const float* ebase = eg + (size_t)b * TT * HH + h;
    float* obase = o + (size_t)b * TT * DD + h * HD + col;

    float4 q0[2], k0[2], q1[2], k1[2];
    float vb0, vb1, e0, e1;

#define LOADSTAGE(Q, Kv, VB, E, tstep)                                           \
    {                                                                            \
        const float* p = abase + (size_t)(tstep) * CONV;                         \
        const float4* pq = (const float4*)(p + dbase);                           \
        const float4* pk = (const float4*)(p + DD + dbase);                      \
        Q[0] = __ldg(pq + 0); Q[1] = __ldg(pq + 1);                              \
        Kv[0] = __ldg(pk + 0); Kv[1] = __ldg(pk + 1);                            \
        VB = __ldg(p + 2 * DD + col);                                            \
        E = __ldg(ebase + (size_t)(tstep) * HH);                                 \
    }

#define DOSTEP(Q, Kv, VB, E, tstep, PFQ, PFK, PFVB, PFE)                         \
    {                                                                            \
        float qq[8], kk[8];                                                      \
        *(float4*)(qq + 0) = Q[0]; *(float4*)(qq + 4) = Q[1];                    \
        *(float4*)(kk + 0) = Kv[0]; *(float4*)(kk + 4) = Kv[1];                  \
        float e = E, v = VB;                                                     \
        if ((tstep) + 2 < TT) LOADSTAGE(PFQ, PFK, PFVB, PFE, (tstep) + 2);       \
        float dot = 0.f;                                                         \
        _Pragma("unroll")                                                        \
        for (int i = 0; i < 8; i++) {                                            \
            S[i] = S[i] * e + kk[i] * v;                                         \
            dot += qq[i] * S[i];                                                 \
        }                                                                        \
        dot += __shfl_xor_sync(0xffffffffu, dot, 1);                             \
        dot += __shfl_xor_sync(0xffffffffu, dot, 2);                             \
        dot += __shfl_xor_sync(0xffffffffu, dot, 4);                             \
        if (part == 0) obase[(size_t)(tstep) * DD] = dot;                        \
    }

    LOADSTAGE(q0, k0, vb0, e0, 0);
    LOADSTAGE(q1, k1, vb1, e1, 1);

    for (int t = 0; t < TT; t += 2) {
        DOSTEP(q0, k0, vb0, e0, t,     q0, k0, vb0, e0);
        DOSTEP(q1, k1, vb1, e1, t + 1, q1, k1, vb1, e1);
    }
#undef LOADSTAGE
#undef DOSTEP
}

// ---------------- gated RMSNorm over head dim ----------------
__global__ __launch_bounds__(128) void post_kernel(float* __restrict__ o,
                                                   const float* __restrict__ z) {
    int w = blockIdx.x * 4 + (threadIdx.x >> 5);
    int lane = threadIdx.x & 31;
    int m = w >> 4;
    int h = w & (HH - 1);
    float* ob = o + (size_t)m * DD + h * HD;
    const float* zb = z + (size_t)m * DD + h * HD;

    float o0 = ob[lane], o1 = ob[lane + 32];
    float s = o0 * o0 + o1 * o1;
#pragma unroll
    for (int off = 16; off; off >>= 1) s += __shfl_xor_sync(0xffffffffu, s, off);
    float r = rsqrtf(s * (1.f / 64.f) + 1e-6f);

    float z0 = zb[lane], z1 = zb[lane + 32];
    float g0 = z0 / (1.f + expf(-z0));
    float g1 = z1 / (1.f + expf(-z1));
    ob[lane] = o0 * r * g0;
    ob[lane + 32] = o1 * r * g1;
}

// ---------------- launch ----------------
extern "C" void kernel_launch(void* const* d_in, const int* in_sizes, int n_in,
                              void* d_out, int out_size) {
    const float* x       = (const float*)d_in[0];
    const float* W_qkv   = (const float*)d_in[1];
    const float* conv_w  = (const float*)d_in[2];
    const float* W_z     = (const float*)d_in[3];
    const float* W_b     = (const float*)d_in[4];
    const float* W_a     = (const float*)d_in[5];
    const float* dt_bias = (const float*)d_in[6];
    const float* A_log   = (const float*)d_in[7];
    const float* W_out   = (const float*)d_in[8];
    float* out = (float*)d_out;

    void *p_mixed, *p_act, *p_z, *p_att, *p_eg, *p_o;
    cudaGetSymbolAddress(&p_mixed, g_mixed);
    cudaGetSymbolAddress(&p_act,   g_act);
    cudaGetSymbolAddress(&p_z,     g_z);
    cudaGetSymbolAddress(&p_att,   g_att);
    cudaGetSymbolAddress(&p_eg,    g_eg);
    cudaGetSymbolAddress(&p_o,     g_o);
    float* mixed = (float*)p_mixed;
    float* act   = (float*)p_act;
    float* zbuf  = (float*)p_z;
    float* att   = (float*)p_att;
    float* egb   = (float*)p_eg;
    float* obuf  = (float*)p_o;

    cudaFuncSetAttribute(tgemm_nt, cudaFuncAttributeMaxDynamicSharedMemorySize, GSMEM);

    // 1. qkv projection: [4096,3072]  (tensor cores, tf32, double-buffered)
    tgemm_nt<<<dim3(CONV / GBN, MM / GBM), 256, GSMEM>>>(x, W_qkv, mixed, MM, CONV, DD);
    // 2. z projection: [4096,1024]
    tgemm_nt<<<dim3(DD / GBN, MM / GBM), 256, GSMEM>>>(x, W_z, zbuf, MM, DD, DD);
    // 3. beta/g raw dots
    att_kernel<<<MM, 256>>>(x, W_b, W_a, att);
    // 4. causal depthwise conv + silu (strip-mined)
    conv_silu_kernel<<<((MM / 8) * (CONV / 4)) / 256, 256>>>(mixed, conv_w, act);
    // 5. l2norm q/k, v*beta, eg
    prep_kernel<<<(MM * HH) / 4, 128>>>(act, att, dt_bias, A_log, egb);
    // 6. sequential scan (8 col-groups)
    scan_kernel<<<BB * HH * 8, 64>>>(act, egb, obuf);
    // 7. gated rmsnorm
    post_kernel<<<(MM * HH) / 4, 128>>>(obuf, zbuf);
    // 8. output projection -> d_out
    tgemm_nt<<<dim3(DD / GBN, MM / GBM), 256, GSMEM>>>(obuf, W_out, out, MM, DD, DD);
}

// round 4
// speedup vs baseline: 2.3514x; 1.0691x over previous
#include <cuda_runtime.h>
#include <cuda_bf16.h>
#include <cstdint>

// ---------------- problem constants ----------------
#define BB 2
#define TT 2048
#define DD 1024
#define HH 16
#define KK 4
#define HD 64
#define CONV (3*DD)
#define MM (BB*TT)          // 4096 tokens

// ---------------- device scratch ----------------
__device__ float g_mixed[(size_t)MM * CONV];   // qkv pre-conv
__device__ float g_act[(size_t)MM * CONV];     // post conv+silu, then normalized q/k, v*beta
__device__ float g_z[(size_t)MM * DD];
__device__ float g_att[(size_t)MM * 2 * HH];   // raw dots
__device__ float g_eg[(size_t)MM * HH];        // exp(g)
__device__ float g_o[(size_t)MM * DD];         // scan output -> gated (tf32-rounded) in place
// tf32 pre-converted operands
__device__ uint32_t g_xtf[(size_t)MM * DD];
__device__ uint32_t g_wq_tf[(size_t)CONV * DD];
__device__ uint32_t g_wz_tf[(size_t)DD * DD];
__device__ uint32_t g_wo_tf[(size_t)DD * DD];

__device__ __forceinline__ uint32_t f2tf32(float x) {
    uint32_t u;
    asm("cvt.rna.tf32.f32 %0, %1;" : "=r"(u) : "f"(x));
    return u;
}

__device__ __forceinline__ uint32_t smem_u32(const void* p) {
    uint32_t a;
    asm("{ .reg .u64 t; cvta.to.shared.u64 t, %1; cvt.u32.u64 %0, t; }" : "=r"(a) : "l"(p));
    return a;
}

// ---------------- tf32 cvt pre-pass ----------------
__global__ __launch_bounds__(256) void cvt_tf32_kernel(const float4* __restrict__ src,
                                                       uint4* __restrict__ dst, int n4) {
    int i = blockIdx.x * 256 + threadIdx.x;
    if (i < n4) {
        float4 v = src[i];
        dst[i] = make_uint4(f2tf32(v.x), f2tf32(v.y), f2tf32(v.z), f2tf32(v.w));
    }
}

// ---------------- tf32 tensor-core GEMM: C[M,N] = A[M,K] @ W[N,K]^T ----------------
// 128 threads = 4 warps (2x2), block 128x128x32, warp tile 64x64.
// Operands pre-converted to tf32. cp.async 16B staging, double buffered.
#define GBM 128
#define GBN 128
#define GBK 32
#define KST 36                   // padded row stride (words)
#define ATILE (GBM * KST)        // 4608 words
#define BUFW (2 * ATILE)         // A + B per buffer
#define GSMEM (2 * BUFW * 4)     // 73728 bytes

__global__ __launch_bounds__(128) void tgemm_nt(const uint32_t* __restrict__ A,
                                                const uint32_t* __restrict__ W,
                                                float* __restrict__ C,
                                                int M, int N, int Kd) {
    extern __shared__ uint32_t sm[];
    int tid = threadIdx.x;
    int wid = tid >> 5;
    int lane = tid & 31;
    int bm = blockIdx.y * GBM;
    int bn = blockIdx.x * GBN;
    int wm = (wid & 1) * 64;
    int wn = (wid >> 1) * 64;
    int g = lane >> 2;
    int tg = lane & 3;

    // staging: quarter-warp per row, 16 rows per pass, 8 passes
    int srow = tid >> 3;          // 0..15
    int sk = (tid & 7) * 4;       // 0..28

    const uint32_t* Ap = A + (size_t)(bm + srow) * Kd + sk;
    const uint32_t* Wp = W + (size_t)(bn + srow) * Kd + sk;
    uint32_t smbase = smem_u32(sm);

    float acc[4][8][4];
#pragma unroll
    for (int i = 0; i < 4; i++)
#pragma unroll
        for (int j = 0; j < 8; j++)
#pragma unroll
            for (int c = 0; c < 4; c++) acc[i][j][c] = 0.f;

#define STAGE(itx)                                                               \
    {                                                                            \
        uint32_t boff = ((itx) & 1) * (BUFW * 4);                                \
        int ko = (itx) * GBK;                                                    \
        _Pragma("unroll")                                                        \
        for (int p = 0; p < 8; p++) {                                            \
            uint32_t da = smbase + boff + ((srow + p * 16) * KST + sk) * 4;      \
            uint32_t db = da + ATILE * 4;                                        \
            const uint32_t* ga = Ap + (size_t)(p * 16) * Kd + ko;                \
            const uint32_t* gb = Wp + (size_t)(p * 16) * Kd + ko;                \
            asm volatile("cp.async.cg.shared.global [%0], [%1], 16;"             \
                         :: "r"(da), "l"(ga));                                   \
            asm volatile("cp.async.cg.shared.global [%0], [%1], 16;"             \
                         :: "r"(db), "l"(gb));                                   \
        }                                                                        \
        asm volatile("cp.async.commit_group;");                                  \
    }

    STAGE(0);

    int ntile = Kd / GBK;
    for (int it = 0; it < ntile; it++) {
        bool more = (it + 1) < ntile;
        if (more) STAGE(it + 1);
        if (more) asm volatile("cp.async.wait_group 1;");
        else      asm volatile("cp.async.wait_group 0;");
        __syncthreads();

        const uint32_t* As = sm + (it & 1) * BUFW;
        const uint32_t* Bs = As + ATILE;

#pragma unroll
        for (int kk = 0; kk < GBK; kk += 8) {
            uint32_t af[4][4];
            uint32_t bf[8][2];
#pragma unroll
            for (int mi = 0; mi < 4; mi++) {
                int r = wm + mi * 16;
                af[mi][0] = As[(r + g) * KST + kk + tg];
                af[mi][1] = As[(r + g + 8) * KST + kk + tg];
                af[mi][2] = As[(r + g) * KST + kk + tg + 4];
                af[mi][3] = As[(r + g + 8) * KST + kk + tg + 4];
            }
#pragma unroll
            for (int ni = 0; ni < 8; ni++) {
                int r = wn + ni * 8;
                bf[ni][0] = Bs[(r + g) * KST + kk + tg];
                bf[ni][1] = Bs[(r + g) * KST + kk + tg + 4];
            }
#pragma unroll
            for (int mi = 0; mi < 4; mi++)
#pragma unroll
                for (int ni = 0; ni < 8; ni++) {
                    asm volatile(
                        "mma.sync.aligned.m16n8k8.row.col.f32.tf32.tf32.f32 "
                        "{%0,%1,%2,%3}, {%4,%5,%6,%7}, {%8,%9}, {%0,%1,%2,%3};"
                        : "+f"(acc[mi][ni][0]), "+f"(acc[mi][ni][1]),
                          "+f"(acc[mi][ni][2]), "+f"(acc[mi][ni][3])
                        : "r"(af[mi][0]), "r"(af[mi][1]), "r"(af[mi][2]), "r"(af[mi][3]),
                          "r"(bf[ni][0]), "r"(bf[ni][1]));
                }
        }
        __syncthreads();
    }
#undef STAGE

    // epilogue
#pragma unroll
    for (int mi = 0; mi < 4; mi++) {
#pragma unroll
        for (int ni = 0; ni < 8; ni++) {
            int row0 = bm + wm + mi * 16 + g;
            int col = bn + wn + ni * 8 + tg * 2;
            *(float2*)(C + (size_t)row0 * N + col) =
                make_float2(acc[mi][ni][0], acc[mi][ni][1]);
            *(float2*)(C + (size_t)(row0 + 8) * N + col) =
                make_float2(acc[mi][ni][2], acc[mi][ni][3]);
        }
    }
}

// ---------------- beta/g raw projections, 8 tokens per block ----------------
__global__ __launch_bounds__(256) void att_kernel(const float* __restrict__ x,
                                                  const float* __restrict__ Wb,
                                                  const float* __restrict__ Wa,
                                                  float* __restrict__ att) {
    __shared__ float xs[8][DD];
    int m0 = blockIdx.x * 8;
    int tid = threadIdx.x;
#pragma unroll
    for (int r = 0; r < 8; r++)
        *(float4*)&xs[r][tid * 4] = *(const float4*)(x + (size_t)(m0 + r) * DD + tid * 4);
    __syncthreads();

    int g = tid >> 3;     // 0..31 output index
    int sub = tid & 7;
    const float* w = (g < HH) ? (Wb + (size_t)g * DD) : (Wa + (size_t)(g - HH) * DD);
    float s[8];
#pragma unroll
    for (int r = 0; r < 8; r++) s[r] = 0.f;

    for (int j = sub * 4; j < DD; j += 32) {
        float4 wv = *(const float4*)(w + j);
#pragma unroll
        for (int r = 0; r < 8; r++) {
            float4 xv = *(const float4*)(&xs[r][j]);
            s[r] += wv.x * xv.x + wv.y * xv.y + wv.z * xv.z + wv.w * xv.w;
        }
    }
#pragma unroll
    for (int r = 0; r < 8; r++) {
        s[r] += __shfl_xor_sync(0xffffffffu, s[r], 4);
        s[r] += __shfl_xor_sync(0xffffffffu, s[r], 2);
        s[r] += __shfl_xor_sync(0xffffffffu, s[r], 1);
        if (sub == 0) att[(size_t)(m0 + r) * 32 + g] = s[r];
    }
}

// ---------------- causal depthwise conv (K=4) + SiLU, strip-mined 8 t/thread ----------------
__global__ __launch_bounds__(256) void conv_silu_kernel(const float* __restrict__ mixed,
                                                        const float* __restrict__ cw,
                                                        float* __restrict__ out) {
    int idx = blockIdx.x * 256 + threadIdx.x;
    int c4 = idx % (CONV / 4);
    int mb = idx / (CONV / 4);
    int m0 = mb * 8;
    int t0 = m0 & (TT - 1);
    int c = c4 * 4;

    float4 w0 = *(const float4*)(cw + (size_t)(c + 0) * KK);
    float4 w1 = *(const float4*)(cw + (size_t)(c + 1) * KK);
    float4 w2 = *(const float4*)(cw + (size_t)(c + 2) * KK);
    float4 w3 = *(const float4*)(cw + (size_t)(c + 3) * KK);
    const float* wp0 = (const float*)&w0;
    const float* wp1 = (const float*)&w1;
    const float* wp2 = (const float*)&w2;
    const float* wp3 = (const float*)&w3;

    float4 win[4];
    const float4 zero4 = make_float4(0.f, 0.f, 0.f, 0.f);
#pragma unroll
    for (int s = 0; s < 3; s++) {
        win[s] = (t0 - 3 + s >= 0)
               ? *(const float4*)(mixed + (size_t)(m0 - 3 + s) * CONV + c)
               : zero4;
    }

#pragma unroll
    for (int tt = 0; tt < 8; tt++) {
        win[3] = *(const float4*)(mixed + (size_t)(m0 + tt) * CONV + c);
        float a0 = 0.f, a1 = 0.f, a2 = 0.f, a3 = 0.f;
#pragma unroll
        for (int j = 0; j < KK; j++) {
            a0 += wp0[j] * win[j].x;
            a1 += wp1[j] * win[j].y;
            a2 += wp2[j] * win[j].z;
            a3 += wp3[j] * win[j].w;
        }
        float4 r;
        r.x = a0 / (1.f + expf(-a0));
        r.y = a1 / (1.f + expf(-a1));
        r.z = a2 / (1.f + expf(-a2));
        r.w = a3 / (1.f + expf(-a3));
        *(float4*)(out + (size_t)(m0 + tt) * CONV + c) = r;
        win[0] = win[1]; win[1] = win[2]; win[2] = win[3];
    }
}

// ---------------- per-(m,h): l2norm q/k, v*=beta, eg=exp(g) ----------------
__global__ __launch_bounds__(128) void prep_kernel(float* __restrict__ act,
                                                   const float* __restrict__ att,
                                                   const float* __restrict__ dt_bias,
                                                   const float* __restrict__ A_log,
                                                   float* __restrict__ eg) {
    int w = blockIdx.x * 4 + (threadIdx.x >> 5);
    int lane = threadIdx.x & 31;
    int m = w >> 4;
    int h = w & (HH - 1);
    float* base = act + (size_t)m * CONV + h * HD;

    float q0 = base[lane], q1 = base[lane + 32];
    float sq = q0 * q0 + q1 * q1;
#pragma unroll
    for (int o = 16; o; o >>= 1) sq += __shfl_xor_sync(0xffffffffu, sq, o);
    float invq = rsqrtf(sq + 1e-6f) * 0.125f;
    base[lane] = q0 * invq;
    base[lane + 32] = q1 * invq;

    float k0 = base[DD + lane], k1 = base[DD + lane + 32];
    float sk = k0 * k0 + k1 * k1;
#pragma unroll
    for (int o = 16; o; o >>= 1) sk += __shfl_xor_sync(0xffffffffu, sk, o);
    float invk = rsqrtf(sk + 1e-6f);
    base[DD + lane] = k0 * invk;
    base[DD + lane + 32] = k1 * invk;

    float bdot = att[(size_t)m * 32 + h];
    float adot = att[(size_t)m * 32 + HH + h];
    float beta = 1.f / (1.f + expf(-bdot));
    float spin = adot + dt_bias[h];
    float sp = (spin > 20.f) ? spin : log1pf(expf(spin));
    float gg = -expf(A_log[h]) * sp;

    base[2 * DD + lane] *= beta;
    base[2 * DD + lane + 32] *= beta;
    if (lane == 0) eg[(size_t)m * HH + h] = expf(gg);
}

// ---------------- sequential gated scan ----------------
__global__ __launch_bounds__(64) void scan_kernel(const float* __restrict__ act,
                                                  const float* __restrict__ eg,
                                                  float* __restrict__ o) {
    int bh = blockIdx.x >> 3;
    int cg = blockIdx.x & 7;
    int b = bh >> 4;
    int h = bh & (HH - 1);
    int tid = threadIdx.x;
    int col = cg * 8 + (tid >> 3);
    int part = tid & 7;
    int dbase = part * 8;

    float S[8];
#pragma unroll
    for (int i = 0; i < 8; i++) S[i] = 0.f;

    const float* abase = act + (size_t)b * TT * CONV + h * HD;
    const float* ebase = eg + (size_t)b * TT * HH + h;
    float* obase = o + (size_t)b * TT * DD + h * HD + col;

    float4 q0[2], k0[2], q1[2], k1[2];
    float vb0, vb1, e0, e1;

#define LOADSTAGE(Q, Kv, VB, E, tstep)                                           \
    {                                                                            \
        const float* p = abase + (size_t)(tstep) * CONV;                         \
        const float4* pq = (const float4*)(p + dbase);                           \
        const float4* pk = (const float4*)(p + DD + dbase);                      \
        Q[0] = __ldg(pq + 0); Q[1] = __ldg(pq + 1);                              \
        Kv[0] = __ldg(pk + 0); Kv[1] = __ldg(pk + 1);                            \
        VB = __ldg(p + 2 * DD + col);                                            \
        E = __ldg(ebase + (size_t)(tstep) * HH);                                 \
    }

#define DOSTEP(Q, Kv, VB, E, tstep, PFQ, PFK, PFVB, PFE)                         \
    {                                                                            \
        float qq[8], kk[8];                                                      \
        *(float4*)(qq + 0) = Q[0]; *(float4*)(qq + 4) = Q[1];                    \
        *(float4*)(kk + 0) = Kv[0]; *(float4*)(kk + 4) = Kv[1];                  \
        float e = E, v = VB;                                                     \
        if ((tstep) + 2 < TT) LOADSTAGE(PFQ, PFK, PFVB, PFE, (tstep) + 2);       \
        float dot = 0.f;                                                         \
        _Pragma("unroll")                                                        \
        for (int i = 0; i < 8; i++) {                                            \
            S[i] = S[i] * e + kk[i] * v;                                         \
            dot += qq[i] * S[i];                                                 \
        }                                                                        \
        dot += __shfl_xor_sync(0xffffffffu, dot, 1);                             \
        dot += __shfl_xor_sync(0xffffffffu, dot, 2);                             \
        dot += __shfl_xor_sync(0xffffffffu, dot, 4);                             \
        if (part == 0) obase[(size_t)(tstep) * DD] = dot;                        \
    }

    LOADSTAGE(q0, k0, vb0, e0, 0);
    LOADSTAGE(q1, k1, vb1, e1, 1);

    for (int t = 0; t < TT; t += 2) {
        DOSTEP(q0, k0, vb0, e0, t,     q0, k0, vb0, e0);
        DOSTEP(q1, k1, vb1, e1, t + 1, q1, k1, vb1, e1);
    }
#undef LOADSTAGE
#undef DOSTEP
}

// ---------------- gated RMSNorm over head dim, output rounded to tf32 ----------------
__global__ __launch_bounds__(128) void post_kernel(float* __restrict__ o,
                                                   const float* __restrict__ z) {
    int w = blockIdx.x * 4 + (threadIdx.x >> 5);
    int lane = threadIdx.x & 31;
    int m = w >> 4;
    int h = w & (HH - 1);
    float* ob = o + (size_t)m * DD + h * HD;
    const float* zb = z + (size_t)m * DD + h * HD;

    float o0 = ob[lane], o1 = ob[lane + 32];
    float s = o0 * o0 + o1 * o1;
#pragma unroll
    for (int off = 16; off; off >>= 1) s += __shfl_xor_sync(0xffffffffu, s, off);
    float r = rsqrtf(s * (1.f / 64.f) + 1e-6f);

    float z0 = zb[lane], z1 = zb[lane + 32];
    float g0 = z0 / (1.f + expf(-z0));
    float g1 = z1 / (1.f + expf(-z1));
    ob[lane]      = __uint_as_float(f2tf32(o0 * r * g0));
    ob[lane + 32] = __uint_as_float(f2tf32(o1 * r * g1));
}

// ---------------- launch ----------------
extern "C" void kernel_launch(void* const* d_in, const int* in_sizes, int n_in,
                              void* d_out, int out_size) {
    const float* x       = (const float*)d_in[0];
    const float* W_qkv   = (const float*)d_in[1];
    const float* conv_w  = (const float*)d_in[2];
    const float* W_z     = (const float*)d_in[3];
    const float* W_b     = (const float*)d_in[4];
    const float* W_a     = (const float*)d_in[5];
    const float* dt_bias = (const float*)d_in[6];
    const float* A_log   = (const float*)d_in[7];
    const float* W_out   = (const float*)d_in[8];
    float* out = (float*)d_out;

    void *p_mixed, *p_act, *p_z, *p_att, *p_eg, *p_o;
    void *p_xtf, *p_wq, *p_wz, *p_wo;
    cudaGetSymbolAddress(&p_mixed, g_mixed);
    cudaGetSymbolAddress(&p_act,   g_act);
    cudaGetSymbolAddress(&p_z,     g_z);
    cudaGetSymbolAddress(&p_att,   g_att);
    cudaGetSymbolAddress(&p_eg,    g_eg);
    cudaGetSymbolAddress(&p_o,     g_o);
    cudaGetSymbolAddress(&p_xtf,   g_xtf);
    cudaGetSymbolAddress(&p_wq,    g_wq_tf);
    cudaGetSymbolAddress(&p_wz,    g_wz_tf);
    cudaGetSymbolAddress(&p_wo,    g_wo_tf);
    float* mixed = (float*)p_mixed;
    float* act   = (float*)p_act;
    float* zbuf  = (float*)p_z;
    float* att   = (float*)p_att;
    float* egb   = (float*)p_eg;
    float* obuf  = (float*)p_o;
    uint32_t* xtf = (uint32_t*)p_xtf;
    uint32_t* wqt = (uint32_t*)p_wq;
    uint32_t* wzt = (uint32_t*)p_wz;
    uint32_t* wot = (uint32_t*)p_wo;

    cudaFuncSetAttribute(tgemm_nt, cudaFuncAttributeMaxDynamicSharedMemorySize, GSMEM);

    // 0. tf32 pre-conversion
    cvt_tf32_kernel<<<(MM * DD / 4) / 256, 256>>>((const float4*)x, (uint4*)xtf, MM * DD / 4);
    cvt_tf32_kernel<<<(CONV * DD / 4) / 256, 256>>>((const float4*)W_qkv, (uint4*)wqt, CONV * DD / 4);
    cvt_tf32_kernel<<<(DD * DD / 4) / 256, 256>>>((const float4*)W_z, (uint4*)wzt, DD * DD / 4);
    cvt_tf32_kernel<<<(DD * DD / 4) / 256, 256>>>((const float4*)W_out, (uint4*)wot, DD * DD / 4);

    // 1. qkv projection: [4096,3072]
    tgemm_nt<<<dim3(CONV / GBN, MM / GBM), 128, GSMEM>>>(xtf, wqt, mixed, MM, CONV, DD);
    // 2. z projection: [4096,1024]
    tgemm_nt<<<dim3(DD / GBN, MM / GBM), 128, GSMEM>>>(xtf, wzt, zbuf, MM, DD, DD);
    // 3. beta/g raw dots (8 tokens/block)
    att_kernel<<<MM / 8, 256>>>(x, W_b, W_a, att);
    // 4. causal depthwise conv + silu
    conv_silu_kernel<<<((MM / 8) * (CONV / 4)) / 256, 256>>>(mixed, conv_w, act);
    // 5. l2norm q/k, v*beta, eg
    prep_kernel<<<(MM * HH) / 4, 128>>>(act, att, dt_bias, A_log, egb);
    // 6. sequential scan
    scan_kernel<<<BB * HH * 8, 64>>>(act, egb, obuf);
    // 7. gated rmsnorm (+ tf32 rounding of output)
    post_kernel<<<(MM * HH) / 4, 128>>>(obuf, zbuf);
    // 8. output projection -> d_out (obuf already tf32-valued)
    tgemm_nt<<<dim3(DD / GBN, MM / GBM), 128, GSMEM>>>((const uint32_t*)obuf, wot, out, MM, DD, DD);
}

// round 6
// speedup vs baseline: 2.4326x; 1.0345x over previous
#include <cuda_runtime.h>
#include <cuda_fp16.h>
#include <cstdint>

// ---------------- problem constants ----------------
#define BB 2
#define TT 2048
#define DD 1024
#define HH 16
#define KK 4
#define HD 64
#define CONV (3*DD)
#define MM (BB*TT)          // 4096 tokens

// ---------------- device scratch ----------------
__device__ float g_mixed[(size_t)MM * CONV];   // qkv pre-conv
__device__ float g_act[(size_t)MM * CONV];     // post conv+silu, then normalized q/k, v*beta
__device__ float g_z[(size_t)MM * DD];
__device__ float g_att[(size_t)MM * 2 * HH];   // raw dots
__device__ float g_eg[(size_t)MM * HH];        // exp(g)
__device__ float g_o[(size_t)MM * DD];         // scan output (float)
// fp16 pre-converted GEMM operands
__device__ __half g_xh[(size_t)MM * DD];
__device__ __half g_wqh[(size_t)CONV * DD];
__device__ __half g_wzh[(size_t)DD * DD];
__device__ __half g_woh[(size_t)DD * DD];
__device__ __half g_oh[(size_t)MM * DD];       // gated rmsnorm output (fp16)

__device__ __forceinline__ uint32_t smem_u32(const void* p) {
    uint32_t a;
    asm("{ .reg .u64 t; cvta.to.shared.u64 t, %1; cvt.u32.u64 %0, t; }" : "=r"(a) : "l"(p));
    return a;
}

// ---------------- fp16 cvt pre-pass ----------------
__global__ __launch_bounds__(256) void cvt_h_kernel(const float4* __restrict__ src,
                                                    uint2* __restrict__ dst, int n4) {
    int i = blockIdx.x * 256 + threadIdx.x;
    if (i < n4) {
        float4 v = src[i];
        __half2 lo = __floats2half2_rn(v.x, v.y);
        __half2 hi = __floats2half2_rn(v.z, v.w);
        dst[i] = make_uint2(*(uint32_t*)&lo, *(uint32_t*)&hi);
    }
}

// ---------------- fp16 tensor-core GEMM: C[M,N] = A[M,K] @ W[N,K]^T ----------------
// 128 threads = 4 warps (2x2), block 128x128x32, warp tile 64x64.
// mma.sync.m16n8k16.f16 : 2 k-steps per 32-k tile. cp.async double-buffered.
// SMEM rows stored as 16 half2-pairs padded to 20 (20r+c mod 32 partitions -> conflict-free).
#define GBK 32
#define KPH 20                    // pair stride per row
#define TILEW (128 * KPH)         // words per tile (2560)
#define BUFW (2 * TILEW)          // A + B per buffer

__global__ __launch_bounds__(128) void hgemm_nt(const __half* __restrict__ A,
                                                const __half* __restrict__ W,
                                                float* __restrict__ C,
                                                int M, int N, int Kd) {
    __shared__ uint32_t sm[2 * BUFW];   // 40960 B
    int tid = threadIdx.x;
    int wid = tid >> 5;
    int lane = tid & 31;
    int bm = blockIdx.y * 128;
    int bn = blockIdx.x * 128;
    int wm = (wid & 1) * 64;
    int wn = (wid >> 1) * 64;
    int g = lane >> 2;
    int tg = lane & 3;

    uint32_t smbase = smem_u32(sm);
    // staging: thread owns one row (tid), 4 chunks of 16B for A and for B
    const __half* Ap = A + (size_t)(bm + tid) * Kd;
    const __half* Wp = W + (size_t)(bn + tid) * Kd;

    float acc[4][8][4];
#pragma unroll
    for (int i = 0; i < 4; i++)
#pragma unroll
        for (int j = 0; j < 8; j++)
#pragma unroll
            for (int c = 0; c < 4; c++) acc[i][j][c] = 0.f;

#define STAGE(itx)                                                               \
    {                                                                            \
        uint32_t boff = smbase + ((itx) & 1) * (BUFW * 4);                       \
        int ko = (itx) * GBK;                                                    \
        uint32_t drow = boff + tid * (KPH * 4);                                  \
        _Pragma("unroll")                                                        \
        for (int c = 0; c < 4; c++) {                                            \
            asm volatile("cp.async.cg.shared.global [%0], [%1], 16;"             \
                         :: "r"(drow + c * 16), "l"(Ap + ko + c * 8));           \
            asm volatile("cp.async.cg.shared.global [%0], [%1], 16;"             \
                         :: "r"(drow + TILEW * 4 + c * 16), "l"(Wp + ko + c * 8)); \
        }                                                                        \
        asm volatile("cp.async.commit_group;");                                  \
    }

    STAGE(0);

    int ntile = Kd / GBK;
    for (int it = 0; it < ntile; it++) {
        bool more = (it + 1) < ntile;
        if (more) STAGE(it + 1);
        if (more) asm volatile("cp.async.wait_group 1;");
        else      asm volatile("cp.async.wait_group 0;");
        __syncthreads();

        const uint32_t* As = sm + (it & 1) * BUFW;
        const uint32_t* Bs = As + TILEW;

#pragma unroll
        for (int ks = 0; ks < 2; ks++) {
            int koff = ks * 8;     // pair offset for this k16 step
            uint32_t af[4][4];
            uint32_t bf[8][2];
#pragma unroll
            for (int mi = 0; mi < 4; mi++) {
                int r = wm + mi * 16;
                af[mi][0] = As[(r + g) * KPH + tg + koff];
                af[mi][1] = As[(r + g + 8) * KPH + tg + koff];
                af[mi][2] = As[(r + g) * KPH + tg + 4 + koff];
                af[mi][3] = As[(r + g + 8) * KPH + tg + 4 + koff];
            }
#pragma unroll
            for (int ni = 0; ni < 8; ni++) {
                int r = wn + ni * 8;
                bf[ni][0] = Bs[(r + g) * KPH + tg + koff];
                bf[ni][1] = Bs[(r + g) * KPH + tg + 4 + koff];
            }
#pragma unroll
            for (int mi = 0; mi < 4; mi++)
#pragma unroll
                for (int ni = 0; ni < 8; ni++) {
                    asm volatile(
                        "mma.sync.aligned.m16n8k16.row.col.f32.f16.f16.f32 "
                        "{%0,%1,%2,%3}, {%4,%5,%6,%7}, {%8,%9}, {%0,%1,%2,%3};"
                        : "+f"(acc[mi][ni][0]), "+f"(acc[mi][ni][1]),
                          "+f"(acc[mi][ni][2]), "+f"(acc[mi][ni][3])
                        : "r"(af[mi][0]), "r"(af[mi][1]), "r"(af[mi][2]), "r"(af[mi][3]),
                          "r"(bf[ni][0]), "r"(bf[ni][1]));
                }
        }
        __syncthreads();
    }
#undef STAGE

    // epilogue
#pragma unroll
    for (int mi = 0; mi < 4; mi++) {
#pragma unroll
        for (int ni = 0; ni < 8; ni++) {
            int row0 = bm + wm + mi * 16 + g;
            int col = bn + wn + ni * 8 + tg * 2;
            *(float2*)(C + (size_t)row0 * N + col) =
                make_float2(acc[mi][ni][0], acc[mi][ni][1]);
            *(float2*)(C + (size_t)(row0 + 8) * N + col) =
                make_float2(acc[mi][ni][2], acc[mi][ni][3]);
        }
    }
}

// ---------------- beta/g raw projections, 8 tokens per block ----------------
__global__ __launch_bounds__(256) void att_kernel(const float* __restrict__ x,
                                                  const float* __restrict__ Wb,
                                                  const float* __restrict__ Wa,
                                                  float* __restrict__ att) {
    __shared__ float xs[8][DD];
    int m0 = blockIdx.x * 8;
    int tid = threadIdx.x;
#pragma unroll
    for (int r = 0; r < 8; r++)
        *(float4*)&xs[r][tid * 4] = *(const float4*)(x + (size_t)(m0 + r) * DD + tid * 4);
    __syncthreads();

    int g = tid >> 3;
    int sub = tid & 7;
    const float* w = (g < HH) ? (Wb + (size_t)g * DD) : (Wa + (size_t)(g - HH) * DD);
    float s[8];
#pragma unroll
    for (int r = 0; r < 8; r++) s[r] = 0.f;

    for (int j = sub * 4; j < DD; j += 32) {
        float4 wv = *(const float4*)(w + j);
#pragma unroll
        for (int r = 0; r < 8; r++) {
            float4 xv = *(const float4*)(&xs[r][j]);
            s[r] += wv.x * xv.x + wv.y * xv.y + wv.z * xv.z + wv.w * xv.w;
        }
    }
#pragma unroll
    for (int r = 0; r < 8; r++) {
        s[r] += __shfl_xor_sync(0xffffffffu, s[r], 4);
        s[r] += __shfl_xor_sync(0xffffffffu, s[r], 2);
        s[r] += __shfl_xor_sync(0xffffffffu, s[r], 1);
        if (sub == 0) att[(size_t)(m0 + r) * 32 + g] = s[r];
    }
}

// ---------------- causal depthwise conv (K=4) + SiLU, strip-mined 8 t/thread ----------------
__global__ __launch_bounds__(256) void conv_silu_kernel(const float* __restrict__ mixed,
                                                        const float* __restrict__ cw,
                                                        float* __restrict__ out) {
    int idx = blockIdx.x * 256 + threadIdx.x;
    int c4 = idx % (CONV / 4);
    int mb = idx / (CONV / 4);
    int m0 = mb * 8;
    int t0 = m0 & (TT - 1);
    int c = c4 * 4;

    float4 w0 = *(const float4*)(cw + (size_t)(c + 0) * KK);
    float4 w1 = *(const float4*)(cw + (size_t)(c + 1) * KK);
    float4 w2 = *(const float4*)(cw + (size_t)(c + 2) * KK);
    float4 w3 = *(const float4*)(cw + (size_t)(c + 3) * KK);
    const float* wp0 = (const float*)&w0;
    const float* wp1 = (const float*)&w1;
    const float* wp2 = (const float*)&w2;
    const float* wp3 = (const float*)&w3;

    float4 win[4];
    const float4 zero4 = make_float4(0.f, 0.f, 0.f, 0.f);
#pragma unroll
    for (int s = 0; s < 3; s++) {
        win[s] = (t0 - 3 + s >= 0)
               ? *(const float4*)(mixed + (size_t)(m0 - 3 + s) * CONV + c)
               : zero4;
    }

#pragma unroll
    for (int tt = 0; tt < 8; tt++) {
        win[3] = *(const float4*)(mixed + (size_t)(m0 + tt) * CONV + c);
        float a0 = 0.f, a1 = 0.f, a2 = 0.f, a3 = 0.f;
#pragma unroll
        for (int j = 0; j < KK; j++) {
            a0 += wp0[j] * win[j].x;
            a1 += wp1[j] * win[j].y;
            a2 += wp2[j] * win[j].z;
            a3 += wp3[j] * win[j].w;
        }
        float4 r;
        r.x = a0 / (1.f + expf(-a0));
        r.y = a1 / (1.f + expf(-a1));
        r.z = a2 / (1.f + expf(-a2));
        r.w = a3 / (1.f + expf(-a3));
        *(float4*)(out + (size_t)(m0 + tt) * CONV + c) = r;
        win[0] = win[1]; win[1] = win[2]; win[2] = win[3];
    }
}

// ---------------- per-(m,h): l2norm q/k, v*=beta, eg=exp(g) ----------------
__global__ __launch_bounds__(128) void prep_kernel(float* __restrict__ act,
                                                   const float* __restrict__ att,
                                                   const float* __restrict__ dt_bias,
                                                   const float* __restrict__ A_log,
                                                   float* __restrict__ eg) {
    int w = blockIdx.x * 4 + (threadIdx.x >> 5);
    int lane = threadIdx.x & 31;
    int m = w >> 4;
    int h = w & (HH - 1);
    float* base = act + (size_t)m * CONV + h * HD;

    float q0 = base[lane], q1 = base[lane + 32];
    float sq = q0 * q0 + q1 * q1;
#pragma unroll
    for (int o = 16; o; o >>= 1) sq += __shfl_xor_sync(0xffffffffu, sq, o);
    float invq = rsqrtf(sq + 1e-6f) * 0.125f;
    base[lane] = q0 * invq;
    base[lane + 32] = q1 * invq;

    float k0 = base[DD + lane], k1 = base[DD + lane + 32];
    float sk = k0 * k0 + k1 * k1;
#pragma unroll
    for (int o = 16; o; o >>= 1) sk += __shfl_xor_sync(0xffffffffu, sk, o);
    float invk = rsqrtf(sk + 1e-6f);
    base[DD + lane] = k0 * invk;
    base[DD + lane + 32] = k1 * invk;

    float bdot = att[(size_t)m * 32 + h];
    float adot = att[(size_t)m * 32 + HH + h];
    float beta = 1.f / (1.f + expf(-bdot));
    float spin = adot + dt_bias[h];
    float sp = (spin > 20.f) ? spin : log1pf(expf(spin));
    float gg = -expf(A_log[h]) * sp;

    base[2 * DD + lane] *= beta;
    base[2 * DD + lane + 32] *= beta;
    if (lane == 0) eg[(size_t)m * HH + h] = expf(gg);
}

// ---------------- sequential gated scan ----------------
__global__ __launch_bounds__(64) void scan_kernel(const float* __restrict__ act,
                                                  const float* __restrict__ eg,
                                                  float* __restrict__ o) {
    int bh = blockIdx.x >> 3;
    int cg = blockIdx.x & 7;
    int b = bh >> 4;
    int h = bh & (HH - 1);
    int tid = threadIdx.x;
    int col = cg * 8 + (tid >> 3);
    int part = tid & 7;
    int dbase = part * 8;

    float S[8];
#pragma unroll
    for (int i = 0; i < 8; i++) S[i] = 0.f;

    const float* abase = act + (size_t)b * TT * CONV + h * HD;
    const float* ebase = eg + (size_t)b * TT * HH + h;
    float* obase = o + (size_t)b * TT * DD + h * HD + col;

    float4 q0[2], k0[2], q1[2], k1[2];
    float vb0, vb1, e0, e1;

#define LOADSTAGE(Q, Kv, VB, E, tstep)                                           \
    {                                                                            \
        const float* p = abase + (size_t)(tstep) * CONV;                         \
        const float4* pq = (const float4*)(p + dbase);                           \
        const float4* pk = (const float4*)(p + DD + dbase);                      \
        Q[0] = __ldg(pq + 0); Q[1] = __ldg(pq + 1);                              \
        Kv[0] = __ldg(pk + 0); Kv[1] = __ldg(pk + 1);                            \
        VB = __ldg(p + 2 * DD + col);                                            \
        E = __ldg(ebase + (size_t)(tstep) * HH);                                 \
    }

#define DOSTEP(Q, Kv, VB, E, tstep, PFQ, PFK, PFVB, PFE)                         \
    {                                                                            \
        float qq[8], kk[8];                                                      \
        *(float4*)(qq + 0) = Q[0]; *(float4*)(qq + 4) = Q[1];                    \
        *(float4*)(kk + 0) = Kv[0]; *(float4*)(kk + 4) = Kv[1];                  \
        float e = E, v = VB;                                                     \
        if ((tstep) + 2 < TT) LOADSTAGE(PFQ, PFK, PFVB, PFE, (tstep) + 2);       \
        float dot = 0.f;                                                         \
        _Pragma("unroll")                                                        \
        for (int i = 0; i < 8; i++) {                                            \
            S[i] = S[i] * e + kk[i] * v;                                         \
            dot += qq[i] * S[i];                                                 \
        }                                                                        \
        dot += __shfl_xor_sync(0xffffffffu, dot, 1);                             \
        dot += __shfl_xor_sync(0xffffffffu, dot, 2);                             \
        dot += __shfl_xor_sync(0xffffffffu, dot, 4);                             \
        if (part == 0) obase[(size_t)(tstep) * DD] = dot;                        \
    }

    LOADSTAGE(q0, k0, vb0, e0, 0);
    LOADSTAGE(q1, k1, vb1, e1, 1);

    for (int t = 0; t < TT; t += 2) {
        DOSTEP(q0, k0, vb0, e0, t,     q0, k0, vb0, e0);
        DOSTEP(q1, k1, vb1, e1, t + 1, q1, k1, vb1, e1);
    }
#undef LOADSTAGE
#undef DOSTEP
}

// ---------------- gated RMSNorm over head dim -> fp16 for final projection ----------------
__global__ __launch_bounds__(128) void post_kernel(const float* __restrict__ o,
                                                   const float* __restrict__ z,
                                                   __half* __restrict__ oh) {
    int w = blockIdx.x * 4 + (threadIdx.x >> 5);
    int lane = threadIdx.x & 31;
    int m = w >> 4;
    int h = w & (HH - 1);
    const float* ob = o + (size_t)m * DD + h * HD;
    const float* zb = z + (size_t)m * DD + h * HD;
    __half* oo = oh + (size_t)m * DD + h * HD;

    float o0 = ob[lane], o1 = ob[lane + 32];
    float s = o0 * o0 + o1 * o1;
#pragma unroll
    for (int off = 16; off; off >>= 1) s += __shfl_xor_sync(0xffffffffu, s, off);
    float r = rsqrtf(s * (1.f / 64.f) + 1e-6f);

    float z0 = zb[lane], z1 = zb[lane + 32];
    float g0 = z0 / (1.f + expf(-z0));
    float g1 = z1 / (1.f + expf(-z1));
    oo[lane]      = __float2half_rn(o0 * r * g0);
    oo[lane + 32] = __float2half_rn(o1 * r * g1);
}

// ---------------- launch ----------------
extern "C" void kernel_launch(void* const* d_in, const int* in_sizes, int n_in,
                              void* d_out, int out_size) {
    const float* x       = (const float*)d_in[0];
    const float* W_qkv   = (const float*)d_in[1];
    const float* conv_w  = (const float*)d_in[2];
    const float* W_z     = (const float*)d_in[3];
    const float* W_b     = (const float*)d_in[4];
    const float* W_a     = (const float*)d_in[5];
    const float* dt_bias = (const float*)d_in[6];
    const float* A_log   = (const float*)d_in[7];
    const float* W_out   = (const float*)d_in[8];
    float* out = (float*)d_out;

    void *p_mixed, *p_act, *p_z, *p_att, *p_eg, *p_o;
    void *p_xh, *p_wq, *p_wz, *p_wo, *p_oh;
    cudaGetSymbolAddress(&p_mixed, g_mixed);
    cudaGetSymbolAddress(&p_act,   g_act);
    cudaGetSymbolAddress(&p_z,     g_z);
    cudaGetSymbolAddress(&p_att,   g_att);
    cudaGetSymbolAddress(&p_eg,    g_eg);
    cudaGetSymbolAddress(&p_o,     g_o);
    cudaGetSymbolAddress(&p_xh,    g_xh);
    cudaGetSymbolAddress(&p_wq,    g_wqh);
    cudaGetSymbolAddress(&p_wz,    g_wzh);
    cudaGetSymbolAddress(&p_wo,    g_woh);
    cudaGetSymbolAddress(&p_oh,    g_oh);
    float* mixed = (float*)p_mixed;
    float* act   = (float*)p_act;
    float* zbuf  = (float*)p_z;
    float* att   = (float*)p_att;
    float* egb   = (float*)p_eg;
    float* obuf  = (float*)p_o;
    __half* xh  = (__half*)p_xh;
    __half* wqh = (__half*)p_wq;
    __half* wzh = (__half*)p_wz;
    __half* woh = (__half*)p_wo;
    __half* oh  = (__half*)p_oh;

    // 0. fp16 pre-conversion
    cvt_h_kernel<<<(MM * DD / 4) / 256, 256>>>((const float4*)x, (uint2*)xh, MM * DD / 4);
    cvt_h_kernel<<<(CONV * DD / 4) / 256, 256>>>((const float4*)W_qkv, (uint2*)wqh, CONV * DD / 4);
    cvt_h_kernel<<<(DD * DD / 4) / 256, 256>>>((const float4*)W_z, (uint2*)wzh, DD * DD / 4);
    cvt_h_kernel<<<(DD * DD / 4) / 256, 256>>>((const float4*)W_out, (uint2*)woh, DD * DD / 4);

    // 1. qkv projection: [4096,3072]  (fp16 mma, fp32 accum)
    hgemm_nt<<<dim3(CONV / 128, MM / 128), 128>>>(xh, wqh, mixed, MM, CONV, DD);
    // 2. z projection: [4096,1024]
    hgemm_nt<<<dim3(DD / 128, MM / 128), 128>>>(xh, wzh, zbuf, MM, DD, DD);
    // 3. beta/g raw dots (8 tokens/block)
    att_kernel<<<MM / 8, 256>>>(x, W_b, W_a, att);
    // 4. causal depthwise conv + silu
    conv_silu_kernel<<<((MM / 8) * (CONV / 4)) / 256, 256>>>(mixed, conv_w, act);
    // 5. l2norm q/k, v*beta, eg
    prep_kernel<<<(MM * HH) / 4, 128>>>(act, att, dt_bias, A_log, egb);
    // 6. sequential scan
    scan_kernel<<<BB * HH * 8, 64>>>(act, egb, obuf);
    // 7. gated rmsnorm -> fp16
    post_kernel<<<(MM * HH) / 4, 128>>>(obuf, zbuf, oh);
    // 8. output projection -> d_out
    hgemm_nt<<<dim3(DD / 128, MM / 128), 128>>>(oh, woh, out, MM, DD, DD);
}

// round 8
// speedup vs baseline: 3.4202x; 1.4060x over previous
#include <cuda_runtime.h>
#include <cuda_fp16.h>
#include <cstdint>

// ---------------- problem constants ----------------
#define BB 2
#define TT 2048
#define DD 1024
#define HH 16
#define KK 4
#define HD 64
#define CONV (3*DD)
#define MM (BB*TT)          // 4096 tokens

// ---------------- device scratch ----------------
__device__ float g_mixed[(size_t)MM * CONV];   // qkv pre-conv
__device__ float g_act[(size_t)MM * CONV];     // post conv+silu, then normalized q/k, v*beta
__device__ float g_z[(size_t)MM * DD];
__device__ float g_att[(size_t)MM * 2 * HH];   // raw dots
__device__ float g_eg[(size_t)MM * HH];        // exp(g)
__device__ float g_o[(size_t)MM * DD];         // scan output (float)
// fp16 pre-converted GEMM operands
__device__ __half g_xh[(size_t)MM * DD];
__device__ __half g_wqh[(size_t)CONV * DD];
__device__ __half g_wzh[(size_t)DD * DD];
__device__ __half g_woh[(size_t)DD * DD];
__device__ __half g_oh[(size_t)MM * DD];       // gated rmsnorm output (fp16)

__device__ __forceinline__ uint32_t smem_u32(const void* p) {
    uint32_t a;
    asm("{ .reg .u64 t; cvta.to.shared.u64 t, %1; cvt.u32.u64 %0, t; }" : "=r"(a) : "l"(p));
    return a;
}

// ---------------- fp16 cvt pre-pass ----------------
__global__ __launch_bounds__(256) void cvt_h_kernel(const float4* __restrict__ src,
                                                    uint2* __restrict__ dst, int n4) {
    int i = blockIdx.x * 256 + threadIdx.x;
    if (i < n4) {
        float4 v = src[i];
        __half2 lo = __floats2half2_rn(v.x, v.y);
        __half2 hi = __floats2half2_rn(v.z, v.w);
        dst[i] = make_uint2(*(uint32_t*)&lo, *(uint32_t*)&hi);
    }
}

// ---------------- fp16 tensor-core GEMM: C[M,N] = A[M,K] @ W[N,K]^T ----------------
#define GBK 32
#define KPH 20                    // pair stride per row
#define TILEW (128 * KPH)         // words per tile (2560)
#define BUFW (2 * TILEW)          // A + B per buffer

__global__ __launch_bounds__(128) void hgemm_nt(const __half* __restrict__ A,
                                                const __half* __restrict__ W,
                                                float* __restrict__ C,
                                                int M, int N, int Kd) {
    __shared__ uint32_t sm[2 * BUFW];   // 40960 B
    int tid = threadIdx.x;
    int wid = tid >> 5;
    int lane = tid & 31;
    int bm = blockIdx.y * 128;
    int bn = blockIdx.x * 128;
    int wm = (wid & 1) * 64;
    int wn = (wid >> 1) * 64;
    int g = lane >> 2;
    int tg = lane & 3;

    uint32_t smbase = smem_u32(sm);
    const __half* Ap = A + (size_t)(bm + tid) * Kd;
    const __half* Wp = W + (size_t)(bn + tid) * Kd;

    float acc[4][8][4];
#pragma unroll
    for (int i = 0; i < 4; i++)
#pragma unroll
        for (int j = 0; j < 8; j++)
#pragma unroll
            for (int c = 0; c < 4; c++) acc[i][j][c] = 0.f;

#define STAGE(itx)                                                               \
    {                                                                            \
        uint32_t boff = smbase + ((itx) & 1) * (BUFW * 4);                       \
        int ko = (itx) * GBK;                                                    \
        uint32_t drow = boff + tid * (KPH * 4);                                  \
        _Pragma("unroll")                                                        \
        for (int c = 0; c < 4; c++) {                                            \
            asm volatile("cp.async.cg.shared.global [%0], [%1], 16;"             \
                         :: "r"(drow + c * 16), "l"(Ap + ko + c * 8));           \
            asm volatile("cp.async.cg.shared.global [%0], [%1], 16;"             \
                         :: "r"(drow + TILEW * 4 + c * 16), "l"(Wp + ko + c * 8)); \
        }                                                                        \
        asm volatile("cp.async.commit_group;");                                  \
    }

    STAGE(0);

    int ntile = Kd / GBK;
    for (int it = 0; it < ntile; it++) {
        bool more = (it + 1) < ntile;
        if (more) STAGE(it + 1);
        if (more) asm volatile("cp.async.wait_group 1;");
        else      asm volatile("cp.async.wait_group 0;");
        __syncthreads();

        const uint32_t* As = sm + (it & 1) * BUFW;
        const uint32_t* Bs = As + TILEW;

#pragma unroll
        for (int ks = 0; ks < 2; ks++) {
            int koff = ks * 8;
            uint32_t af[4][4];
            uint32_t bf[8][2];
#pragma unroll
            for (int mi = 0; mi < 4; mi++) {
                int r = wm + mi * 16;
                af[mi][0] = As[(r + g) * KPH + tg + koff];
                af[mi][1] = As[(r + g + 8) * KPH + tg + koff];
                af[mi][2] = As[(r + g) * KPH + tg + 4 + koff];
                af[mi][3] = As[(r + g + 8) * KPH + tg + 4 + koff];
            }
#pragma unroll
            for (int ni = 0; ni < 8; ni++) {
                int r = wn + ni * 8;
                bf[ni][0] = Bs[(r + g) * KPH + tg + koff];
                bf[ni][1] = Bs[(r + g) * KPH + tg + 4 + koff];
            }
#pragma unroll
            for (int mi = 0; mi < 4; mi++)
#pragma unroll
                for (int ni = 0; ni < 8; ni++) {
                    asm volatile(
                        "mma.sync.aligned.m16n8k16.row.col.f32.f16.f16.f32 "
                        "{%0,%1,%2,%3}, {%4,%5,%6,%7}, {%8,%9}, {%0,%1,%2,%3};"
                        : "+f"(acc[mi][ni][0]), "+f"(acc[mi][ni][1]),
                          "+f"(acc[mi][ni][2]), "+f"(acc[mi][ni][3])
                        : "r"(af[mi][0]), "r"(af[mi][1]), "r"(af[mi][2]), "r"(af[mi][3]),
                          "r"(bf[ni][0]), "r"(bf[ni][1]));
                }
        }
        __syncthreads();
    }
#undef STAGE

#pragma unroll
    for (int mi = 0; mi < 4; mi++) {
#pragma unroll
        for (int ni = 0; ni < 8; ni++) {
            int row0 = bm + wm + mi * 16 + g;
            int col = bn + wn + ni * 8 + tg * 2;
            *(float2*)(C + (size_t)row0 * N + col) =
                make_float2(acc[mi][ni][0], acc[mi][ni][1]);
            *(float2*)(C + (size_t)(row0 + 8) * N + col) =
                make_float2(acc[mi][ni][2], acc[mi][ni][3]);
        }
    }
}

// ---------------- beta/g raw projections, 8 tokens per block ----------------
__global__ __launch_bounds__(256) void att_kernel(const float* __restrict__ x,
                                                  const float* __restrict__ Wb,
                                                  const float* __restrict__ Wa,
                                                  float* __restrict__ att) {
    __shared__ float xs[8][DD];
    int m0 = blockIdx.x * 8;
    int tid = threadIdx.x;
#pragma unroll
    for (int r = 0; r < 8; r++)
        *(float4*)&xs[r][tid * 4] = *(const float4*)(x + (size_t)(m0 + r) * DD + tid * 4);
    __syncthreads();

    int g = tid >> 3;
    int sub = tid & 7;
    const float* w = (g < HH) ? (Wb + (size_t)g * DD) : (Wa + (size_t)(g - HH) * DD);
    float s[8];
#pragma unroll
    for (int r = 0; r < 8; r++) s[r] = 0.f;

    for (int j = sub * 4; j < DD; j += 32) {
        float4 wv = *(const float4*)(w + j);
#pragma unroll
        for (int r = 0; r < 8; r++) {
            float4 xv = *(const float4*)(&xs[r][j]);
            s[r] += wv.x * xv.x + wv.y * xv.y + wv.z * xv.z + wv.w * xv.w;
        }
    }
#pragma unroll
    for (int r = 0; r < 8; r++) {
        s[r] += __shfl_xor_sync(0xffffffffu, s[r], 4);
        s[r] += __shfl_xor_sync(0xffffffffu, s[r], 2);
        s[r] += __shfl_xor_sync(0xffffffffu, s[r], 1);
        if (sub == 0) att[(size_t)(m0 + r) * 32 + g] = s[r];
    }
}

// ---------------- causal depthwise conv (K=4) + SiLU, strip-mined 8 t/thread ----------------
__global__ __launch_bounds__(256) void conv_silu_kernel(const float* __restrict__ mixed,
                                                        const float* __restrict__ cw,
                                                        float* __restrict__ out) {
    int idx = blockIdx.x * 256 + threadIdx.x;
    int c4 = idx % (CONV / 4);
    int mb = idx / (CONV / 4);
    int m0 = mb * 8;
    int t0 = m0 & (TT - 1);
    int c = c4 * 4;

    float4 w0 = *(const float4*)(cw + (size_t)(c + 0) * KK);
    float4 w1 = *(const float4*)(cw + (size_t)(c + 1) * KK);
    float4 w2 = *(const float4*)(cw + (size_t)(c + 2) * KK);
    float4 w3 = *(const float4*)(cw + (size_t)(c + 3) * KK);
    const float* wp0 = (const float*)&w0;
    const float* wp1 = (const float*)&w1;
    const float* wp2 = (const float*)&w2;
    const float* wp3 = (const float*)&w3;

    float4 win[4];
    const float4 zero4 = make_float4(0.f, 0.f, 0.f, 0.f);
#pragma unroll
    for (int s = 0; s < 3; s++) {
        win[s] = (t0 - 3 + s >= 0)
               ? *(const float4*)(mixed + (size_t)(m0 - 3 + s) * CONV + c)
               : zero4;
    }

#pragma unroll
    for (int tt = 0; tt < 8; tt++) {
        win[3] = *(const float4*)(mixed + (size_t)(m0 + tt) * CONV + c);
        float a0 = 0.f, a1 = 0.f, a2 = 0.f, a3 = 0.f;
#pragma unroll
        for (int j = 0; j < KK; j++) {
            a0 += wp0[j] * win[j].x;
            a1 += wp1[j] * win[j].y;
            a2 += wp2[j] * win[j].z;
            a3 += wp3[j] * win[j].w;
        }
        float4 r;
        r.x = a0 / (1.f + expf(-a0));
        r.y = a1 / (1.f + expf(-a1));
        r.z = a2 / (1.f + expf(-a2));
        r.w = a3 / (1.f + expf(-a3));
        *(float4*)(out + (size_t)(m0 + tt) * CONV + c) = r;
        win[0] = win[1]; win[1] = win[2]; win[2] = win[3];
    }
}

// ---------------- per-(m,h): l2norm q/k, v*=beta, eg=exp(g) ----------------
__global__ __launch_bounds__(128) void prep_kernel(float* __restrict__ act,
                                                   const float* __restrict__ att,
                                                   const float* __restrict__ dt_bias,
                                                   const float* __restrict__ A_log,
                                                   float* __restrict__ eg) {
    int w = blockIdx.x * 4 + (threadIdx.x >> 5);
    int lane = threadIdx.x & 31;
    int m = w >> 4;
    int h = w & (HH - 1);
    float* base = act + (size_t)m * CONV + h * HD;

    float q0 = base[lane], q1 = base[lane + 32];
    float sq = q0 * q0 + q1 * q1;
#pragma unroll
    for (int o = 16; o; o >>= 1) sq += __shfl_xor_sync(0xffffffffu, sq, o);
    float invq = rsqrtf(sq + 1e-6f) * 0.125f;
    base[lane] = q0 * invq;
    base[lane + 32] = q1 * invq;

    float k0 = base[DD + lane], k1 = base[DD + lane + 32];
    float sk = k0 * k0 + k1 * k1;
#pragma unroll
    for (int o = 16; o; o >>= 1) sk += __shfl_xor_sync(0xffffffffu, sk, o);
    float invk = rsqrtf(sk + 1e-6f);
    base[DD + lane] = k0 * invk;
    base[DD + lane + 32] = k1 * invk;

    float bdot = att[(size_t)m * 32 + h];
    float adot = att[(size_t)m * 32 + HH + h];
    float beta = 1.f / (1.f + expf(-bdot));
    float spin = adot + dt_bias[h];
    float sp = (spin > 20.f) ? spin : log1pf(expf(spin));
    float gg = -expf(A_log[h]) * sp;

    base[2 * DD + lane] *= beta;
    base[2 * DD + lane + 32] *= beta;
    if (lane == 0) eg[(size_t)m * HH + h] = expf(gg);
}

// ---------------- sequential gated scan, smem chunk-staged ----------------
// grid 256 = 32 (b,h) * 8 col-groups ; 64 threads.
// Chunks of CH=16 timesteps staged into smem via cp.async (double-buffered).
#define CH 16
#define NCH (TT / CH)

__global__ __launch_bounds__(64) void scan_kernel(const float* __restrict__ act,
                                                  const float* __restrict__ eg,
                                                  float* __restrict__ o) {
    __shared__ float sq[2][CH][64];
    __shared__ float sk[2][CH][64];
    __shared__ float sv[2][CH][8];
    __shared__ float se[2][CH];

    int bh = blockIdx.x >> 3;
    int cg = blockIdx.x & 7;
    int b = bh >> 4;
    int h = bh & (HH - 1);
    int tid = threadIdx.x;
    int vloc = tid >> 3;          // 0..7 local v column
    int part = tid & 7;
    int dbase = part * 8;
    int col = cg * 8 + vloc;

    float S[8];
#pragma unroll
    for (int i = 0; i < 8; i++) S[i] = 0.f;

    const float* abase = act + (size_t)b * TT * CONV + h * HD;
    const float* ebase = eg + ((size_t)b * TT) * HH + h;
    float* obase = o + (size_t)b * TT * DD + h * HD + col;

    // staging assignment: thread -> (row srow in chunk, quarter sq4)
    int srow = tid >> 2;          // 0..15
    int sq4 = (tid & 3) * 16;     // float offset of 64B quarter

    uint32_t aq = smem_u32(&sq[0][0][0]);
    uint32_t ak = smem_u32(&sk[0][0][0]);
    uint32_t av = smem_u32(&sv[0][0][0]);
    uint32_t ae = smem_u32(&se[0][0]);

#define SSTAGE(cx)                                                                \
    {                                                                             \
        int bufx = (cx) & 1;                                                      \
        int t0 = (cx) * CH;                                                       \
        const float* gq = abase + (size_t)(t0 + srow) * CONV + sq4;               \
        const float* gk = gq + DD;                                                \
        uint32_t dq = aq + (bufx * CH * 64 + srow * 64 + sq4) * 4;                \
        uint32_t dk = ak + (bufx * CH * 64 + srow * 64 + sq4) * 4;                \
        _Pragma("unroll")                                                         \
        for (int j = 0; j < 4; j++) {                                             \
            asm volatile("cp.async.cg.shared.global [%0], [%1], 16;"              \
                         :: "r"(dq + j * 16), "l"(gq + j * 4));                   \
            asm volatile("cp.async.cg.shared.global [%0], [%1], 16;"              \
                         :: "r"(dk + j * 16), "l"(gk + j * 4));                   \
        }                                                                         \
        if (tid < 32) {                                                           \
            int tv = tid >> 1;                                                    \
            int c2 = (tid & 1) * 4;                                               \
            const float* gv = abase + (size_t)(t0 + tv) * CONV + 2 * DD           \
                              + cg * 8 + c2;                                      \
            uint32_t dv = av + (bufx * CH * 8 + tv * 8 + c2) * 4;                 \
            asm volatile("cp.async.ca.shared.global [%0], [%1], 16;"              \
                         :: "r"(dv), "l"(gv));                                    \
        }                                                                         \
        if (tid < 16) {                                                           \
            const float* ge = ebase + (size_t)(t0 + tid) * HH;                    \
            uint32_t de = ae + (bufx * CH + tid) * 4;                             \
            asm volatile("cp.async.ca.shared.global [%0], [%1], 4;"               \
                         :: "r"(de), "l"(ge));                                    \
        }                                                                         \
        asm volatile("cp.async.commit_group;");                                   \
    }

    SSTAGE(0);

    for (int c = 0; c < NCH; c++) {
        bool more = (c + 1) < NCH;
        if (more) SSTAGE(c + 1);
        if (more) asm volatile("cp.async.wait_group 1;");
        else      asm volatile("cp.async.wait_group 0;");
        __syncthreads();

        int buf = c & 1;
#pragma unroll
        for (int tt = 0; tt < CH; tt++) {
            float qq[8], kk[8];
            *(float4*)(qq + 0) = *(const float4*)(&sq[buf][tt][dbase]);
            *(float4*)(qq + 4) = *(const float4*)(&sq[buf][tt][dbase + 4]);
            *(float4*)(kk + 0) = *(const float4*)(&sk[buf][tt][dbase]);
            *(float4*)(kk + 4) = *(const float4*)(&sk[buf][tt][dbase + 4]);
            float v = sv[buf][tt][vloc];
            float e = se[buf][tt];
            float dot = 0.f;
#pragma unroll
            for (int i = 0; i < 8; i++) {
                S[i] = S[i] * e + kk[i] * v;
                dot += qq[i] * S[i];
            }
            dot += __shfl_xor_sync(0xffffffffu, dot, 1);
            dot += __shfl_xor_sync(0xffffffffu, dot, 2);
            dot += __shfl_xor_sync(0xffffffffu, dot, 4);
            if (part == 0) obase[(size_t)(c * CH + tt) * DD] = dot;
        }
        __syncthreads();
    }
#undef SSTAGE
}

// ---------------- gated RMSNorm over head dim -> fp16 for final projection ----------------
__global__ __launch_bounds__(128) void post_kernel(const float* __restrict__ o,
                                                   const float* __restrict__ z,
                                                   __half* __restrict__ oh) {
    int w = blockIdx.x * 4 + (threadIdx.x >> 5);
    int lane = threadIdx.x & 31;
    int m = w >> 4;
    int h = w & (HH - 1);
    const float* ob = o + (size_t)m * DD + h * HD;
    const float* zb = z + (size_t)m * DD + h * HD;
    __half* oo = oh + (size_t)m * DD + h * HD;

    float o0 = ob[lane], o1 = ob[lane + 32];
    float s = o0 * o0 + o1 * o1;
#pragma unroll
    for (int off = 16; off; off >>= 1) s += __shfl_xor_sync(0xffffffffu, s, off);
    float r = rsqrtf(s * (1.f / 64.f) + 1e-6f);

    float z0 = zb[lane], z1 = zb[lane + 32];
    float g0 = z0 / (1.f + expf(-z0));
    float g1 = z1 / (1.f + expf(-z1));
    oo[lane]      = __float2half_rn(o0 * r * g0);
    oo[lane + 32] = __float2half_rn(o1 * r * g1);
}

// ---------------- launch ----------------
extern "C" void kernel_launch(void* const* d_in, const int* in_sizes, int n_in,
                              void* d_out, int out_size) {
    const float* x       = (const float*)d_in[0];
    const float* W_qkv   = (const float*)d_in[1];
    const float* conv_w  = (const float*)d_in[2];
    const float* W_z     = (const float*)d_in[3];
    const float* W_b     = (const float*)d_in[4];
    const float* W_a     = (const float*)d_in[5];
    const float* dt_bias = (const float*)d_in[6];
    const float* A_log   = (const float*)d_in[7];
    const float* W_out   = (const float*)d_in[8];
    float* out = (float*)d_out;

    void *p_mixed, *p_act, *p_z, *p_att, *p_eg, *p_o;
    void *p_xh, *p_wq, *p_wz, *p_wo, *p_oh;
    cudaGetSymbolAddress(&p_mixed, g_mixed);
    cudaGetSymbolAddress(&p_act,   g_act);
    cudaGetSymbolAddress(&p_z,     g_z);
    cudaGetSymbolAddress(&p_att,   g_att);
    cudaGetSymbolAddress(&p_eg,    g_eg);
    cudaGetSymbolAddress(&p_o,     g_o);
    cudaGetSymbolAddress(&p_xh,    g_xh);
    cudaGetSymbolAddress(&p_wq,    g_wqh);
    cudaGetSymbolAddress(&p_wz,    g_wzh);
    cudaGetSymbolAddress(&p_wo,    g_woh);
    cudaGetSymbolAddress(&p_oh,    g_oh);
    float* mixed = (float*)p_mixed;
    float* act   = (float*)p_act;
    float* zbuf  = (float*)p_z;
    float* att   = (float*)p_att;
    float* egb   = (float*)p_eg;
    float* obuf  = (float*)p_o;
    __half* xh  = (__half*)p_xh;
    __half* wqh = (__half*)p_wq;
    __half* wzh = (__half*)p_wz;
    __half* woh = (__half*)p_wo;
    __half* oh  = (__half*)p_oh;

    // 0. fp16 pre-conversion
    cvt_h_kernel<<<(MM * DD / 4) / 256, 256>>>((const float4*)x, (uint2*)xh, MM * DD / 4);
    cvt_h_kernel<<<(CONV * DD / 4) / 256, 256>>>((const float4*)W_qkv, (uint2*)wqh, CONV * DD / 4);
    cvt_h_kernel<<<(DD * DD / 4) / 256, 256>>>((const float4*)W_z, (uint2*)wzh, DD * DD / 4);
    cvt_h_kernel<<<(DD * DD / 4) / 256, 256>>>((const float4*)W_out, (uint2*)woh, DD * DD / 4);

    // 1. qkv projection: [4096,3072]  (fp16 mma, fp32 accum)
    hgemm_nt<<<dim3(CONV / 128, MM / 128), 128>>>(xh, wqh, mixed, MM, CONV, DD);
    // 2. z projection: [4096,1024]
    hgemm_nt<<<dim3(DD / 128, MM / 128), 128>>>(xh, wzh, zbuf, MM, DD, DD);
    // 3. beta/g raw dots (8 tokens/block)
    att_kernel<<<MM / 8, 256>>>(x, W_b, W_a, att);
    // 4. causal depthwise conv + silu
    conv_silu_kernel<<<((MM / 8) * (CONV / 4)) / 256, 256>>>(mixed, conv_w, act);
    // 5. l2norm q/k, v*beta, eg
    prep_kernel<<<(MM * HH) / 4, 128>>>(act, att, dt_bias, A_log, egb);
    // 6. sequential scan (smem chunk-staged)
    scan_kernel<<<BB * HH * 8, 64>>>(act, egb, obuf);
    // 7. gated rmsnorm -> fp16
    post_kernel<<<(MM * HH) / 4, 128>>>(obuf, zbuf, oh);
    // 8. output projection -> d_out
    hgemm_nt<<<dim3(DD / 128, MM / 128), 128>>>(oh, woh, out, MM, DD, DD);
}